// round 11
// baseline (speedup 1.0000x reference)
#include <cuda_runtime.h>
#include <math.h>
#include <stdint.h>

#define DIMS    256
#define VOCAB   4096
#define HEADS   2
#define NB      2
#define SEQ     1024
#define DH      128
#define TOKENS  (NB * SEQ)
#define NLAYERS 6

// ---------------- scratch ----------------
__device__ float g_x[TOKENS * DIMS];
__device__ float g_q[NB * HEADS * SEQ * DH];     // [b,h,s,d]
__device__ float g_k[NB * HEADS * SEQ * DH];     // [b,h,s,d]
__device__ float g_vt[NB * HEADS * DH * SEQ];    // [b,h,d,s]
__device__ float g_attn[TOKENS * DIMS];
__device__ float g_a[TOKENS * DIMS];
__device__ float g_h[TOKENS * 2 * DIMS];

// ---------------- helpers ----------------
__device__ __forceinline__ uint32_t f2tf32(float f) {
    uint32_t r;
    asm("cvt.rna.tf32.f32 %0, %1;" : "=r"(r) : "f"(f));
    return r;
}
__device__ __forceinline__ void ldm_x4(uint32_t& r0, uint32_t& r1, uint32_t& r2, uint32_t& r3,
                                       uint32_t addr) {
    asm volatile("ldmatrix.sync.aligned.m8n8.x4.shared.b16 {%0,%1,%2,%3}, [%4];"
                 : "=r"(r0), "=r"(r1), "=r"(r2), "=r"(r3) : "r"(addr));
}
__device__ __forceinline__ void mma_tf32(float* c, const uint32_t* a, const uint32_t* b) {
    asm volatile("mma.sync.aligned.m16n8k8.row.col.f32.tf32.tf32.f32 "
                 "{%0,%1,%2,%3}, {%4,%5,%6,%7}, {%8,%9}, {%0,%1,%2,%3};"
                 : "+f"(c[0]), "+f"(c[1]), "+f"(c[2]), "+f"(c[3])
                 : "r"(a[0]), "r"(a[1]), "r"(a[2]), "r"(a[3]), "r"(b[0]), "r"(b[1]));
}

// ---------------- encoder ----------------
__global__ __launch_bounds__(256) void encode_kernel(
    const int* __restrict__ X, const float* __restrict__ W_enc,
    const float* __restrict__ b_enc, float* __restrict__ xout)
{
    const int t = blockIdx.x;
    const int s = t & (SEQ - 1);
    const int tid = threadIdx.x;

    __shared__ float pos[DIMS];
    {
        const int i = tid;
        const float p = (float)NB - (float)s;
        const int fi = (i < DH) ? i : i - DH;
        const float invf = 1.0f / powf(10000.0f, (float)fi * (1.0f / 128.0f));
        const float ang = p * invf;
        pos[i] = (i < DH) ? sinf(ang) : cosf(ang);
    }
    __syncthreads();

    const int tok = X[t];
    const int warp = tid >> 5, lane = tid & 31;

    #pragma unroll
    for (int o = warp; o < DIMS; o += 8) {
        const float* wrow = W_enc + ((size_t)o * VOCAB + tok) * DIMS;
        const float4* w4 = reinterpret_cast<const float4*>(wrow);
        const float4* p4 = reinterpret_cast<const float4*>(pos);
        float4 wa = w4[lane * 2 + 0], wb = w4[lane * 2 + 1];
        float4 pa = p4[lane * 2 + 0], pb = p4[lane * 2 + 1];
        float acc = wa.x * pa.x + wa.y * pa.y + wa.z * pa.z + wa.w * pa.w
                  + wb.x * pb.x + wb.y * pb.y + wb.z * pb.z + wb.w * pb.w;
        #pragma unroll
        for (int off = 16; off; off >>= 1)
            acc += __shfl_down_sync(0xffffffffu, acc, off);
        if (lane == 0)
            xout[t * DIMS + o] = acc + b_enc[o];
    }
}

// ---------------- tf32 GEMM: 128 thr / 4 warps, 32x32 warp tile (R6-validated) ----
enum GemmMode {
    MODE_PLAIN = 0,
    MODE_QKV   = 1,   // z=0: Q [b,h,s,d]; z=1: K [b,h,s,d]; z=2: V^T [b,h,d,s]
    MODE_SILU  = 6,
    MODE_RESADD= 7
};

#define BM 64
#define BN 64
#define BK 16
#define PADK 20

template<int MODE>
__global__ __launch_bounds__(128)
void gemm5(const float* __restrict__ A,
           const float* __restrict__ B0, const float* __restrict__ B1, const float* __restrict__ B2,
           float* __restrict__ C0, float* __restrict__ C1, float* __restrict__ C2,
           const float* __restrict__ R,
           int M, int N, int K)
{
    const int z = blockIdx.z;
    const float* B = B0;
    float* C = C0;
    if (MODE == MODE_QKV) {
        B = (z == 0) ? B0 : (z == 1) ? B1 : B2;
        C = (z == 0) ? C0 : (z == 1) ? C1 : C2;
    }

    const int m0 = blockIdx.y * BM;
    const int n0 = blockIdx.x * BN;

    __shared__ uint32_t As[2][BM * PADK];
    __shared__ uint32_t Bs[2][BN * PADK];

    const int tid  = threadIdx.x;
    const int lane = tid & 31;
    const int wid  = tid >> 5;          // 4 warps
    const int wm   = wid >> 1;          // 0..1 -> m offset wm*32
    const int wn   = wid & 1;           // 0..1 -> n offset wn*32

    // A loader: row = tid>>1 (0..63), half = (tid&1)*8
    const int aRow = tid >> 1;
    const int aColH = (tid & 1) * 8;
    const float* gA = A + (size_t)(m0 + aRow) * K + aColH;

    // B loader: n = tid&63, quads {2*(tid>>6), 2*(tid>>6)+1}
    const int bN = tid & 63;
    const int bQ = (tid >> 6) * 2;
    const float* gB = B + n0 + bN;

    const int grp = lane >> 3, lr = lane & 7;
    const int aRowOff = (grp & 1) * 8 + lr;
    const int aKoff   = (grp >> 1) * 4;
    const int bRowOff = (grp >> 1) * 8 + lr;
    const int bKoff   = (grp & 1) * 4;

    float acc[2][4][4];
    #pragma unroll
    for (int i = 0; i < 2; i++)
        #pragma unroll
        for (int j = 0; j < 4; j++)
            #pragma unroll
            for (int r = 0; r < 4; r++) acc[i][j][r] = 0.f;

    const int nk = K / BK;

    // prologue: stage 0
    {
        float4 ra0 = *reinterpret_cast<const float4*>(gA);
        float4 ra1 = *reinterpret_cast<const float4*>(gA + 4);
        uint4 ua0 = make_uint4(f2tf32(ra0.x), f2tf32(ra0.y), f2tf32(ra0.z), f2tf32(ra0.w));
        uint4 ua1 = make_uint4(f2tf32(ra1.x), f2tf32(ra1.y), f2tf32(ra1.z), f2tf32(ra1.w));
        *reinterpret_cast<uint4*>(&As[0][aRow * PADK + aColH])     = ua0;
        *reinterpret_cast<uint4*>(&As[0][aRow * PADK + aColH + 4]) = ua1;

        #pragma unroll
        for (int q2 = 0; q2 < 2; q2++) {
            const int q = bQ + q2;
            float r0 = gB[(size_t)(q * 4 + 0) * N];
            float r1 = gB[(size_t)(q * 4 + 1) * N];
            float r2 = gB[(size_t)(q * 4 + 2) * N];
            float r3 = gB[(size_t)(q * 4 + 3) * N];
            uint4 ub = make_uint4(f2tf32(r0), f2tf32(r1), f2tf32(r2), f2tf32(r3));
            *reinterpret_cast<uint4*>(&Bs[0][bN * PADK + q * 4]) = ub;
        }
    }
    __syncthreads();

    for (int kt = 0; kt < nk; kt++) {
        const int cur = kt & 1, nxt = cur ^ 1;
        float4 ra0, ra1;
        float rb[8];
        const bool more = (kt + 1 < nk);
        if (more) {
            const float* pA = gA + (kt + 1) * BK;
            ra0 = *reinterpret_cast<const float4*>(pA);
            ra1 = *reinterpret_cast<const float4*>(pA + 4);
            const float* pB = gB + (size_t)(kt + 1) * BK * N;
            #pragma unroll
            for (int q2 = 0; q2 < 2; q2++)
                #pragma unroll
                for (int j = 0; j < 4; j++)
                    rb[q2 * 4 + j] = pB[(size_t)((bQ + q2) * 4 + j) * N];
        }

        const uint32_t aBase = (uint32_t)__cvta_generic_to_shared(&As[cur][0]);
        const uint32_t bBase = (uint32_t)__cvta_generic_to_shared(&Bs[cur][0]);

        #pragma unroll
        for (int kc = 0; kc < 2; kc++) {
            uint32_t af[2][4], bf[4][2];
            #pragma unroll
            for (int mt = 0; mt < 2; mt++) {
                uint32_t addr = aBase + 4u * ((wm * 32 + mt * 16 + aRowOff) * PADK + kc * 8 + aKoff);
                ldm_x4(af[mt][0], af[mt][1], af[mt][2], af[mt][3], addr);
            }
            #pragma unroll
            for (int nt2 = 0; nt2 < 2; nt2++) {
                uint32_t r0, r1, r2, r3;
                uint32_t addr = bBase + 4u * ((wn * 32 + nt2 * 16 + bRowOff) * PADK + kc * 8 + bKoff);
                ldm_x4(r0, r1, r2, r3, addr);
                bf[nt2 * 2 + 0][0] = r0; bf[nt2 * 2 + 0][1] = r1;
                bf[nt2 * 2 + 1][0] = r2; bf[nt2 * 2 + 1][1] = r3;
            }
            #pragma unroll
            for (int mt = 0; mt < 2; mt++)
                #pragma unroll
                for (int nt = 0; nt < 4; nt++)
                    mma_tf32(acc[mt][nt], af[mt], bf[nt]);
        }

        if (more) {
            uint4 ua0 = make_uint4(f2tf32(ra0.x), f2tf32(ra0.y), f2tf32(ra0.z), f2tf32(ra0.w));
            uint4 ua1 = make_uint4(f2tf32(ra1.x), f2tf32(ra1.y), f2tf32(ra1.z), f2tf32(ra1.w));
            *reinterpret_cast<uint4*>(&As[nxt][aRow * PADK + aColH])     = ua0;
            *reinterpret_cast<uint4*>(&As[nxt][aRow * PADK + aColH + 4]) = ua1;
            #pragma unroll
            for (int q2 = 0; q2 < 2; q2++) {
                uint4 ub = make_uint4(f2tf32(rb[q2 * 4 + 0]), f2tf32(rb[q2 * 4 + 1]),
                                      f2tf32(rb[q2 * 4 + 2]), f2tf32(rb[q2 * 4 + 3]));
                *reinterpret_cast<uint4*>(&Bs[nxt][bN * PADK + (bQ + q2) * 4]) = ub;
            }
        }
        __syncthreads();
    }

    // epilogue
    #pragma unroll
    for (int mt = 0; mt < 2; mt++) {
        #pragma unroll
        for (int nt = 0; nt < 4; nt++) {
            const int mrow = m0 + wm * 32 + mt * 16 + (lane >> 2);
            const int ncol = n0 + wn * 32 + nt * 8 + 2 * (lane & 3);
            #pragma unroll
            for (int half = 0; half < 2; half++) {
                const int m = mrow + half * 8;
                float v0 = acc[mt][nt][half * 2 + 0], v1 = acc[mt][nt][half * 2 + 1];
                if (MODE == MODE_PLAIN) {
                    *reinterpret_cast<float2*>(&C[(size_t)m * N + ncol]) = make_float2(v0, v1);
                } else if (MODE == MODE_SILU) {
                    v0 = v0 / (1.f + expf(-v0));
                    v1 = v1 / (1.f + expf(-v1));
                    *reinterpret_cast<float2*>(&C[(size_t)m * N + ncol]) = make_float2(v0, v1);
                } else if (MODE == MODE_RESADD) {
                    float2 r2 = *reinterpret_cast<const float2*>(&R[(size_t)m * N + ncol]);
                    *reinterpret_cast<float2*>(&C[(size_t)m * N + ncol]) =
                        make_float2(v0 + r2.x, v1 + r2.y);
                } else if (MODE == MODE_QKV) {
                    const int b = m / SEQ, srow = m & (SEQ - 1);
                    const int h = ncol / DH, d = ncol & (DH - 1);
                    if (z == 2) {  // V^T [b,h,d,s]
                        C[(((size_t)(b * HEADS + h) * DH) + d + 0) * SEQ + srow] = v0;
                        C[(((size_t)(b * HEADS + h) * DH) + d + 1) * SEQ + srow] = v1;
                    } else {       // Q/K [b,h,s,d]
                        *reinterpret_cast<float2*>(
                            &C[(((size_t)(b * HEADS + h) * SEQ) + srow) * DH + d]) =
                            make_float2(v0, v1);
                    }
                }
            }
        }
    }
}

// ---------------- flash attention, warp-specialized producer/consumer ----------
// 256 thr: warps 0-3 compute, warps 4-7 stage next K/V tile (double-buffered).
#define PADQ 132
#define PADV 68
#define FLASH_SMEM ((32*PADQ + 2*64*PADQ + 2*128*PADV + 32*PADV + 192) * 4)
#define BARC() asm volatile("bar.sync 1, 128;" ::: "memory")

__global__ __launch_bounds__(256)
void flash_kernel(const float* __restrict__ Q, const float* __restrict__ K,
                  const float* __restrict__ Vt, float* __restrict__ Oout)
{
    const int qt = 31 - (int)blockIdx.x;   // heavy blocks first
    const int bh = blockIdx.y;
    const int b = bh >> 1, h = bh & 1;
    const int q0 = qt * 32;
    const float scale = 0.08838834764831845f;  // 1/sqrt(128)

    extern __shared__ unsigned char smraw[];
    uint32_t* Qs  = (uint32_t*)smraw;           // [32][PADQ]
    uint32_t* Ks0 = Qs + 32 * PADQ;             // [2][64][PADQ]
    uint32_t* Vs0 = Ks0 + 2 * 64 * PADQ;        // [2][128][PADV]
    uint32_t* Ps  = Vs0 + 2 * 128 * PADV;       // [32][PADV]
    float* m_s  = (float*)(Ps + 32 * PADV);     // [32]
    float* l_s  = m_s + 32;                     // [32]
    float* wmax = l_s + 32;                     // [2][32]
    float* wsum = wmax + 64;                    // [2][32]

    const int tid = threadIdx.x, lane = tid & 31, wid = tid >> 5;
    const bool producer = (wid >= 4);
    const int ptid = tid - 128;                 // producer thread id 0..127

    const int mh = wid >> 1;                    // consumer: m-half (16 rows)
    const int nh = wid & 1;                     // consumer: n-half
    const int grp = lane >> 3, lr = lane & 7;
    const int aRowOff = (grp & 1) * 8 + lr;
    const int aKoff   = (grp >> 1) * 4;
    const int bRowOff = (grp >> 1) * 8 + lr;
    const int bKoff   = (grp & 1) * 4;
    const int r0 = lane >> 2;
    const int cq = 2 * (lane & 3);

    const float* Qg = Q  + (size_t)bh * SEQ * DH;
    const float* Kg = K  + (size_t)bh * SEQ * DH;
    const float* Vg = Vt + (size_t)bh * DH * SEQ;

    // Q tile -> smem (all 256 threads; 4 float4 each)
    {
        const int r = tid >> 3, part = tid & 7;
        const float* src = Qg + (size_t)(q0 + r) * DH + part * 16;
        uint32_t* dst = Qs + r * PADQ + part * 16;
        #pragma unroll
        for (int j = 0; j < 4; j++) {
            float4 f = reinterpret_cast<const float4*>(src)[j];
            dst[j * 4 + 0] = f2tf32(f.x); dst[j * 4 + 1] = f2tf32(f.y);
            dst[j * 4 + 2] = f2tf32(f.z); dst[j * 4 + 3] = f2tf32(f.w);
        }
    }
    if (tid < 32) { m_s[tid] = -3.0e38f; l_s[tid] = 0.f; }

    const int nkt = (qt >> 1) + 1;

    // producers: load stage 0
    if (producer) {
        const int kr = ptid >> 1, khalf = ptid & 1;
        {
            const float* src = Kg + (size_t)kr * DH + khalf * 64;
            uint32_t* dst = Ks0 + kr * PADQ + khalf * 64;
            #pragma unroll
            for (int j = 0; j < 16; j++) {
                float4 f = reinterpret_cast<const float4*>(src)[j];
                dst[j * 4 + 0] = f2tf32(f.x); dst[j * 4 + 1] = f2tf32(f.y);
                dst[j * 4 + 2] = f2tf32(f.z); dst[j * 4 + 3] = f2tf32(f.w);
            }
        }
        {
            const float* src = Vg + (size_t)ptid * SEQ;
            uint32_t* dst = Vs0 + ptid * PADV;
            #pragma unroll
            for (int j = 0; j < 16; j++) {
                float4 f = reinterpret_cast<const float4*>(src)[j];
                dst[j * 4 + 0] = f2tf32(f.x); dst[j * 4 + 1] = f2tf32(f.y);
                dst[j * 4 + 2] = f2tf32(f.z); dst[j * 4 + 3] = f2tf32(f.w);
            }
        }
    }
    __syncthreads();

    float accO[8][4];
    #pragma unroll
    for (int i = 0; i < 8; i++)
        #pragma unroll
        for (int j = 0; j < 4; j++) accO[i][j] = 0.f;

    const int ridx0 = mh * 16 + r0, ridx1 = ridx0 + 8;

    for (int kt = 0; kt < nkt; kt++) {
        const int cur = kt & 1, nxt = cur ^ 1;

        if (producer) {
            // stage next K/V tile while consumers compute current
            if (kt + 1 < nkt) {
                const int kr = ptid >> 1, khalf = ptid & 1;
                {
                    const float* src = Kg + (size_t)((kt + 1) * 64 + kr) * DH + khalf * 64;
                    uint32_t* dst = Ks0 + nxt * 64 * PADQ + kr * PADQ + khalf * 64;
                    #pragma unroll
                    for (int j = 0; j < 16; j++) {
                        float4 f = reinterpret_cast<const float4*>(src)[j];
                        dst[j * 4 + 0] = f2tf32(f.x); dst[j * 4 + 1] = f2tf32(f.y);
                        dst[j * 4 + 2] = f2tf32(f.z); dst[j * 4 + 3] = f2tf32(f.w);
                    }
                }
                {
                    const float* src = Vg + (size_t)ptid * SEQ + (kt + 1) * 64;
                    uint32_t* dst = Vs0 + nxt * 128 * PADV + ptid * PADV;
                    #pragma unroll
                    for (int j = 0; j < 16; j++) {
                        float4 f = reinterpret_cast<const float4*>(src)[j];
                        dst[j * 4 + 0] = f2tf32(f.x); dst[j * 4 + 1] = f2tf32(f.y);
                        dst[j * 4 + 2] = f2tf32(f.z); dst[j * 4 + 3] = f2tf32(f.w);
                    }
                }
            }
        } else {
            // ---- S = Q K^T ----
            float accS[4][4];
            #pragma unroll
            for (int i = 0; i < 4; i++)
                #pragma unroll
                for (int j = 0; j < 4; j++) accS[i][j] = 0.f;

            const uint32_t qBase = (uint32_t)__cvta_generic_to_shared(Qs);
            const uint32_t kBase = (uint32_t)__cvta_generic_to_shared(Ks0 + cur * 64 * PADQ);
            #pragma unroll
            for (int kc = 0; kc < 16; kc++) {
                uint32_t af[4], bf[4][2];
                {
                    uint32_t addr = qBase + 4u * ((mh * 16 + aRowOff) * PADQ + kc * 8 + aKoff);
                    ldm_x4(af[0], af[1], af[2], af[3], addr);
                }
                #pragma unroll
                for (int nt2 = 0; nt2 < 2; nt2++) {
                    uint32_t t0, t1, t2, t3;
                    uint32_t addr = kBase + 4u * ((nh * 32 + nt2 * 16 + bRowOff) * PADQ + kc * 8 + bKoff);
                    ldm_x4(t0, t1, t2, t3, addr);
                    bf[nt2 * 2 + 0][0] = t0; bf[nt2 * 2 + 0][1] = t1;
                    bf[nt2 * 2 + 1][0] = t2; bf[nt2 * 2 + 1][1] = t3;
                }
                #pragma unroll
                for (int nt = 0; nt < 4; nt++)
                    mma_tf32(accS[nt], af, bf[nt]);
            }

            // scale + causal mask + partial row max
            float pm0 = -3.0e38f, pm1 = -3.0e38f;
            #pragma unroll
            for (int nt = 0; nt < 4; nt++) {
                #pragma unroll
                for (int e = 0; e < 4; e++) {
                    const int half = e >> 1, j = e & 1;
                    const int col = kt * 64 + nh * 32 + nt * 8 + cq + j;
                    const int qr = q0 + mh * 16 + r0 + half * 8;
                    float v = accS[nt][e] * scale;
                    if (col > qr) v = -1.0e30f;
                    accS[nt][e] = v;
                    if (half == 0) pm0 = fmaxf(pm0, v); else pm1 = fmaxf(pm1, v);
                }
            }
            pm0 = fmaxf(pm0, __shfl_xor_sync(0xffffffffu, pm0, 1));
            pm0 = fmaxf(pm0, __shfl_xor_sync(0xffffffffu, pm0, 2));
            pm1 = fmaxf(pm1, __shfl_xor_sync(0xffffffffu, pm1, 1));
            pm1 = fmaxf(pm1, __shfl_xor_sync(0xffffffffu, pm1, 2));
            if ((lane & 3) == 0) {
                wmax[nh * 32 + ridx0] = pm0;
                wmax[nh * 32 + ridx1] = pm1;
            }
            BARC();

            const float mold0 = m_s[ridx0], mold1 = m_s[ridx1];
            const float nm0 = fmaxf(mold0, fmaxf(wmax[ridx0], wmax[32 + ridx0]));
            const float nm1 = fmaxf(mold1, fmaxf(wmax[ridx1], wmax[32 + ridx1]));
            const float fac0 = expf(mold0 - nm0);
            const float fac1 = expf(mold1 - nm1);

            float ps0 = 0.f, ps1 = 0.f;
            #pragma unroll
            for (int nt = 0; nt < 4; nt++) {
                #pragma unroll
                for (int e = 0; e < 4; e++) {
                    const int half = e >> 1, j = e & 1;
                    const float p = expf(accS[nt][e] - (half ? nm1 : nm0));
                    if (half == 0) ps0 += p; else ps1 += p;
                    const int col = nh * 32 + nt * 8 + cq + j;
                    Ps[(mh * 16 + r0 + half * 8) * PADV + col] = f2tf32(p);
                }
            }
            ps0 += __shfl_xor_sync(0xffffffffu, ps0, 1);
            ps0 += __shfl_xor_sync(0xffffffffu, ps0, 2);
            ps1 += __shfl_xor_sync(0xffffffffu, ps1, 1);
            ps1 += __shfl_xor_sync(0xffffffffu, ps1, 2);
            if ((lane & 3) == 0) {
                wsum[nh * 32 + ridx0] = ps0;
                wsum[nh * 32 + ridx1] = ps1;
            }
            #pragma unroll
            for (int nt = 0; nt < 8; nt++) {
                accO[nt][0] *= fac0; accO[nt][1] *= fac0;
                accO[nt][2] *= fac1; accO[nt][3] *= fac1;
            }
            BARC();

            if (nh == 0 && (lane & 3) == 0) {
                m_s[ridx0] = nm0;
                l_s[ridx0] = l_s[ridx0] * fac0 + wsum[ridx0] + wsum[32 + ridx0];
                m_s[ridx1] = nm1;
                l_s[ridx1] = l_s[ridx1] * fac1 + wsum[ridx1] + wsum[32 + ridx1];
            }

            // ---- O += P V ----
            const uint32_t pBase = (uint32_t)__cvta_generic_to_shared(Ps);
            const uint32_t vBase = (uint32_t)__cvta_generic_to_shared(Vs0 + cur * 128 * PADV);
            #pragma unroll
            for (int kc = 0; kc < 8; kc++) {
                uint32_t af[4], bf[8][2];
                {
                    uint32_t addr = pBase + 4u * ((mh * 16 + aRowOff) * PADV + kc * 8 + aKoff);
                    ldm_x4(af[0], af[1], af[2], af[3], addr);
                }
                #pragma unroll
                for (int nt2 = 0; nt2 < 4; nt2++) {
                    uint32_t t0, t1, t2, t3;
                    uint32_t addr = vBase + 4u * ((nh * 64 + nt2 * 16 + bRowOff) * PADV + kc * 8 + bKoff);
                    ldm_x4(t0, t1, t2, t3, addr);
                    bf[nt2 * 2 + 0][0] = t0; bf[nt2 * 2 + 0][1] = t1;
                    bf[nt2 * 2 + 1][0] = t2; bf[nt2 * 2 + 1][1] = t3;
                }
                #pragma unroll
                for (int nt = 0; nt < 8; nt++)
                    mma_tf32(accO[nt], af, bf[nt]);
            }
        }
        __syncthreads();
    }

    // normalize + write head-concat output (consumers only)
    if (!producer) {
        const float inv0 = 1.f / l_s[ridx0];
        const float inv1 = 1.f / l_s[ridx1];
        #pragma unroll
        for (int nt = 0; nt < 8; nt++) {
            const int d = nh * 64 + nt * 8 + cq;
            const int s0 = q0 + ridx0;
            *reinterpret_cast<float2*>(&Oout[((size_t)(b * SEQ) + s0) * DIMS + h * DH + d]) =
                make_float2(accO[nt][0] * inv0, accO[nt][1] * inv0);
            *reinterpret_cast<float2*>(&Oout[((size_t)(b * SEQ) + s0 + 8) * DIMS + h * DH + d]) =
                make_float2(accO[nt][2] * inv1, accO[nt][3] * inv1);
        }
    }
}

// ---------------- driver ----------------
extern "C" void kernel_launch(void* const* d_in, const int* in_sizes, int n_in,
                              void* d_out, int out_size)
{
    const int*   X     = (const int*)  d_in[0];
    const float* W_enc = (const float*)d_in[1];
    const float* b_enc = (const float*)d_in[2];
    const float* Wq    = (const float*)d_in[3];
    const float* Wk    = (const float*)d_in[4];
    const float* Wv    = (const float*)d_in[5];
    const float* Wo    = (const float*)d_in[6];
    const float* W1    = (const float*)d_in[7];
    const float* W2    = (const float*)d_in[8];
    const float* W_dec = (const float*)d_in[9];
    float* out = (float*)d_out;

    float *x, *q, *k, *vt, *attn, *a, *h;
    cudaGetSymbolAddress((void**)&x,    g_x);
    cudaGetSymbolAddress((void**)&q,    g_q);
    cudaGetSymbolAddress((void**)&k,    g_k);
    cudaGetSymbolAddress((void**)&vt,   g_vt);
    cudaGetSymbolAddress((void**)&attn, g_attn);
    cudaGetSymbolAddress((void**)&a,    g_a);
    cudaGetSymbolAddress((void**)&h,    g_h);

    cudaFuncSetAttribute(flash_kernel, cudaFuncAttributeMaxDynamicSharedMemorySize,
                         FLASH_SMEM);

    encode_kernel<<<TOKENS, 256>>>(X, W_enc, b_enc, x);

    const dim3 gQKV(DIMS / BN, TOKENS / BM, 3);
    const dim3 gSq (DIMS / BN, TOKENS / BM, 1);
    const dim3 gFl (32, NB * HEADS, 1);
    const dim3 gM1 (2 * DIMS / BN, TOKENS / BM, 1);
    const dim3 gDec(VOCAB / BN, TOKENS / BM, 1);

    for (int l = 0; l < NLAYERS; l++) {
        const float* wq = Wq + (size_t)l * DIMS * DIMS;
        const float* wk = Wk + (size_t)l * DIMS * DIMS;
        const float* wv = Wv + (size_t)l * DIMS * DIMS;
        const float* wo = Wo + (size_t)l * DIMS * DIMS;
        const float* w1 = W1 + (size_t)l * DIMS * 2 * DIMS;
        const float* w2 = W2 + (size_t)l * 2 * DIMS * DIMS;

        gemm5<MODE_QKV><<<gQKV, 128>>>(x, wq, wk, wv, q, k, vt, nullptr,
                                       TOKENS, DIMS, DIMS);
        flash_kernel<<<gFl, 256, FLASH_SMEM>>>(q, k, vt, attn);
        gemm5<MODE_PLAIN><<<gSq, 128>>>(attn, wo, nullptr, nullptr, a, nullptr, nullptr, nullptr,
                                        TOKENS, DIMS, DIMS);
        gemm5<MODE_SILU><<<gM1, 128>>>(a, w1, nullptr, nullptr, h, nullptr, nullptr, nullptr,
                                       TOKENS, 2 * DIMS, DIMS);
        gemm5<MODE_RESADD><<<gSq, 128>>>(h, w2, nullptr, nullptr, x, nullptr, nullptr, x,
                                         TOKENS, DIMS, 2 * DIMS);
    }

    gemm5<MODE_PLAIN><<<gDec, 128>>>(x, W_dec, nullptr, nullptr, out, nullptr, nullptr, nullptr,
                                     TOKENS, VOCAB, DIMS);
}

// round 12
// speedup vs baseline: 2.0309x; 2.0309x over previous
#include <cuda_runtime.h>
#include <math.h>
#include <stdint.h>

#define DIMS    256
#define VOCAB   4096
#define HEADS   2
#define NB      2
#define SEQ     1024
#define DH      128
#define TOKENS  (NB * SEQ)
#define NLAYERS 6

// ---------------- scratch ----------------
__device__ float g_x[TOKENS * DIMS];
__device__ float g_q[NB * HEADS * SEQ * DH];     // [b,h,s,d]
__device__ float g_k[NB * HEADS * SEQ * DH];     // [b,h,s,d]
__device__ float g_vt[NB * HEADS * DH * SEQ];    // [b,h,d,s]
__device__ float g_attn[TOKENS * DIMS];
__device__ float g_a[TOKENS * DIMS];
__device__ float g_h[TOKENS * 2 * DIMS];

// ---------------- helpers ----------------
__device__ __forceinline__ uint32_t f2tf32(float f) {
    uint32_t r;
    asm("cvt.rna.tf32.f32 %0, %1;" : "=r"(r) : "f"(f));
    return r;
}
__device__ __forceinline__ uint32_t u2tf32(uint32_t u) {
    uint32_t r;
    asm("cvt.rna.tf32.f32 %0, %1;" : "=r"(r) : "f"(__uint_as_float(u)));
    return r;
}
__device__ __forceinline__ void ldm_x4(uint32_t& r0, uint32_t& r1, uint32_t& r2, uint32_t& r3,
                                       uint32_t addr) {
    asm volatile("ldmatrix.sync.aligned.m8n8.x4.shared.b16 {%0,%1,%2,%3}, [%4];"
                 : "=r"(r0), "=r"(r1), "=r"(r2), "=r"(r3) : "r"(addr));
}
__device__ __forceinline__ void mma_tf32(float* c, const uint32_t* a, const uint32_t* b) {
    asm volatile("mma.sync.aligned.m16n8k8.row.col.f32.tf32.tf32.f32 "
                 "{%0,%1,%2,%3}, {%4,%5,%6,%7}, {%8,%9}, {%0,%1,%2,%3};"
                 : "+f"(c[0]), "+f"(c[1]), "+f"(c[2]), "+f"(c[3])
                 : "r"(a[0]), "r"(a[1]), "r"(a[2]), "r"(a[3]), "r"(b[0]), "r"(b[1]));
}
__device__ __forceinline__ void cp16(uint32_t dst, const void* src) {
    asm volatile("cp.async.cg.shared.global [%0], [%1], 16;" :: "r"(dst), "l"(src));
}
#define CP_COMMIT() asm volatile("cp.async.commit_group;" ::: "memory")
#define CP_WAIT1()  asm volatile("cp.async.wait_group 1;" ::: "memory")
#define CP_WAIT0()  asm volatile("cp.async.wait_group 0;" ::: "memory")

// ---------------- encoder ----------------
__global__ __launch_bounds__(256) void encode_kernel(
    const int* __restrict__ X, const float* __restrict__ W_enc,
    const float* __restrict__ b_enc, float* __restrict__ xout)
{
    const int t = blockIdx.x;
    const int s = t & (SEQ - 1);
    const int tid = threadIdx.x;

    __shared__ float pos[DIMS];
    {
        const int i = tid;
        const float p = (float)NB - (float)s;
        const int fi = (i < DH) ? i : i - DH;
        const float invf = 1.0f / powf(10000.0f, (float)fi * (1.0f / 128.0f));
        const float ang = p * invf;
        pos[i] = (i < DH) ? sinf(ang) : cosf(ang);
    }
    __syncthreads();

    const int tok = X[t];
    const int warp = tid >> 5, lane = tid & 31;

    #pragma unroll
    for (int o = warp; o < DIMS; o += 8) {
        const float* wrow = W_enc + ((size_t)o * VOCAB + tok) * DIMS;
        const float4* w4 = reinterpret_cast<const float4*>(wrow);
        const float4* p4 = reinterpret_cast<const float4*>(pos);
        float4 wa = w4[lane * 2 + 0], wb = w4[lane * 2 + 1];
        float4 pa = p4[lane * 2 + 0], pb = p4[lane * 2 + 1];
        float acc = wa.x * pa.x + wa.y * pa.y + wa.z * pa.z + wa.w * pa.w
                  + wb.x * pb.x + wb.y * pb.y + wb.z * pb.z + wb.w * pb.w;
        #pragma unroll
        for (int off = 16; off; off >>= 1)
            acc += __shfl_down_sync(0xffffffffu, acc, off);
        if (lane == 0)
            xout[t * DIMS + o] = acc + b_enc[o];
    }
}

// ---------------- tf32 GEMM: BM=32, BN=64, BK=32, 128 thr / 4 warps ----------
enum GemmMode {
    MODE_PLAIN = 0,
    MODE_QKV   = 1,   // z=0: Q [b,h,s,d]; z=1: K [b,h,s,d]; z=2: V^T [b,h,d,s]
    MODE_SILU  = 6,
    MODE_RESADD= 7
};

#define BM 32
#define BN 64
#define BK 32
#define PADK 36

template<int MODE>
__global__ __launch_bounds__(128)
void gemm6(const float* __restrict__ A,
           const float* __restrict__ B0, const float* __restrict__ B1, const float* __restrict__ B2,
           float* __restrict__ C0, float* __restrict__ C1, float* __restrict__ C2,
           const float* __restrict__ R,
           int M, int N, int K)
{
    const int z = blockIdx.z;
    const float* B = B0;
    float* C = C0;
    if (MODE == MODE_QKV) {
        B = (z == 0) ? B0 : (z == 1) ? B1 : B2;
        C = (z == 0) ? C0 : (z == 1) ? C1 : C2;
    }

    const int m0 = blockIdx.y * BM;
    const int n0 = blockIdx.x * BN;

    __shared__ uint32_t As[2][BM * PADK];
    __shared__ uint32_t Bs[2][BN * PADK];

    const int tid  = threadIdx.x;
    const int lane = tid & 31;
    const int wid  = tid >> 5;          // 4 warps
    const int wm   = wid >> 1;          // 0..1 -> m offset wm*16
    const int wn   = wid & 1;           // 0..1 -> n offset wn*32

    // A loader: 32 rows x 32 k; each thread 8 consecutive k (2 float4)
    const int aRow = tid >> 2;          // 0..31
    const int aCol = (tid & 3) * 8;     // 0,8,16,24
    const float* gA = A + (size_t)(m0 + aRow) * K + aCol;

    // B loader: [n][k] transposed store; each thread 4 k-quads for one n
    const int bN  = tid & 63;
    const int bQ0 = (tid >> 6) * 4;     // quads bQ0..bQ0+3
    const float* gB = B + n0 + bN;

    const int grp = lane >> 3, lr = lane & 7;
    const int aRowOff = (grp & 1) * 8 + lr;
    const int aKoff   = (grp >> 1) * 4;
    const int bRowOff = (grp >> 1) * 8 + lr;
    const int bKoff   = (grp & 1) * 4;

    float acc[4][4];
    #pragma unroll
    for (int j = 0; j < 4; j++)
        #pragma unroll
        for (int r = 0; r < 4; r++) acc[j][r] = 0.f;

    const int nk = K / BK;

    // prologue: stage 0
    {
        float4 ra0 = *reinterpret_cast<const float4*>(gA);
        float4 ra1 = *reinterpret_cast<const float4*>(gA + 4);
        uint4 ua0 = make_uint4(f2tf32(ra0.x), f2tf32(ra0.y), f2tf32(ra0.z), f2tf32(ra0.w));
        uint4 ua1 = make_uint4(f2tf32(ra1.x), f2tf32(ra1.y), f2tf32(ra1.z), f2tf32(ra1.w));
        *reinterpret_cast<uint4*>(&As[0][aRow * PADK + aCol])     = ua0;
        *reinterpret_cast<uint4*>(&As[0][aRow * PADK + aCol + 4]) = ua1;

        #pragma unroll
        for (int q2 = 0; q2 < 4; q2++) {
            const int q = bQ0 + q2;
            float r0 = gB[(size_t)(q * 4 + 0) * N];
            float r1 = gB[(size_t)(q * 4 + 1) * N];
            float r2 = gB[(size_t)(q * 4 + 2) * N];
            float r3 = gB[(size_t)(q * 4 + 3) * N];
            uint4 ub = make_uint4(f2tf32(r0), f2tf32(r1), f2tf32(r2), f2tf32(r3));
            *reinterpret_cast<uint4*>(&Bs[0][bN * PADK + q * 4]) = ub;
        }
    }
    __syncthreads();

    for (int kt = 0; kt < nk; kt++) {
        const int cur = kt & 1, nxt = cur ^ 1;
        float4 ra0, ra1;
        float rb[16];
        const bool more = (kt + 1 < nk);
        if (more) {
            const float* pA = gA + (kt + 1) * BK;
            ra0 = *reinterpret_cast<const float4*>(pA);
            ra1 = *reinterpret_cast<const float4*>(pA + 4);
            const float* pB = gB + (size_t)(kt + 1) * BK * N;
            #pragma unroll
            for (int q2 = 0; q2 < 4; q2++)
                #pragma unroll
                for (int j = 0; j < 4; j++)
                    rb[q2 * 4 + j] = pB[(size_t)((bQ0 + q2) * 4 + j) * N];
        }

        const uint32_t aBase = (uint32_t)__cvta_generic_to_shared(&As[cur][0]);
        const uint32_t bBase = (uint32_t)__cvta_generic_to_shared(&Bs[cur][0]);

        #pragma unroll
        for (int kc = 0; kc < 4; kc++) {
            uint32_t af[4], bf[4][2];
            {
                uint32_t addr = aBase + 4u * ((wm * 16 + aRowOff) * PADK + kc * 8 + aKoff);
                ldm_x4(af[0], af[1], af[2], af[3], addr);
            }
            #pragma unroll
            for (int nt2 = 0; nt2 < 2; nt2++) {
                uint32_t r0, r1, r2, r3;
                uint32_t addr = bBase + 4u * ((wn * 32 + nt2 * 16 + bRowOff) * PADK + kc * 8 + bKoff);
                ldm_x4(r0, r1, r2, r3, addr);
                bf[nt2 * 2 + 0][0] = r0; bf[nt2 * 2 + 0][1] = r1;
                bf[nt2 * 2 + 1][0] = r2; bf[nt2 * 2 + 1][1] = r3;
            }
            #pragma unroll
            for (int nt = 0; nt < 4; nt++)
                mma_tf32(acc[nt], af, bf[nt]);
        }

        if (more) {
            uint4 ua0 = make_uint4(f2tf32(ra0.x), f2tf32(ra0.y), f2tf32(ra0.z), f2tf32(ra0.w));
            uint4 ua1 = make_uint4(f2tf32(ra1.x), f2tf32(ra1.y), f2tf32(ra1.z), f2tf32(ra1.w));
            *reinterpret_cast<uint4*>(&As[nxt][aRow * PADK + aCol])     = ua0;
            *reinterpret_cast<uint4*>(&As[nxt][aRow * PADK + aCol + 4]) = ua1;
            #pragma unroll
            for (int q2 = 0; q2 < 4; q2++) {
                uint4 ub = make_uint4(f2tf32(rb[q2 * 4 + 0]), f2tf32(rb[q2 * 4 + 1]),
                                      f2tf32(rb[q2 * 4 + 2]), f2tf32(rb[q2 * 4 + 3]));
                *reinterpret_cast<uint4*>(&Bs[nxt][bN * PADK + (bQ0 + q2) * 4]) = ub;
            }
        }
        __syncthreads();
    }

    // epilogue
    #pragma unroll
    for (int nt = 0; nt < 4; nt++) {
        const int mrow = m0 + wm * 16 + (lane >> 2);
        const int ncol = n0 + wn * 32 + nt * 8 + 2 * (lane & 3);
        #pragma unroll
        for (int half = 0; half < 2; half++) {
            const int m = mrow + half * 8;
            float v0 = acc[nt][half * 2 + 0], v1 = acc[nt][half * 2 + 1];
            if (MODE == MODE_PLAIN) {
                *reinterpret_cast<float2*>(&C[(size_t)m * N + ncol]) = make_float2(v0, v1);
            } else if (MODE == MODE_SILU) {
                v0 = v0 / (1.f + expf(-v0));
                v1 = v1 / (1.f + expf(-v1));
                *reinterpret_cast<float2*>(&C[(size_t)m * N + ncol]) = make_float2(v0, v1);
            } else if (MODE == MODE_RESADD) {
                float2 r2 = *reinterpret_cast<const float2*>(&R[(size_t)m * N + ncol]);
                *reinterpret_cast<float2*>(&C[(size_t)m * N + ncol]) =
                    make_float2(v0 + r2.x, v1 + r2.y);
            } else if (MODE == MODE_QKV) {
                const int b = m / SEQ, srow = m & (SEQ - 1);
                const int h = ncol / DH, d = ncol & (DH - 1);
                if (z == 2) {  // V^T [b,h,d,s]
                    C[(((size_t)(b * HEADS + h) * DH) + d + 0) * SEQ + srow] = v0;
                    C[(((size_t)(b * HEADS + h) * DH) + d + 1) * SEQ + srow] = v1;
                } else {       // Q/K [b,h,s,d]
                    *reinterpret_cast<float2*>(
                        &C[(((size_t)(b * HEADS + h) * SEQ) + srow) * DH + d]) =
                        make_float2(v0, v1);
                }
            }
        }
    }
}

// ---------------- flash attention: 128 thr, cp.async double-buffered K/V ------
#define PADQ 132
#define PADV 68
#define FLASH_SMEM ((32*PADQ + 2*64*PADQ + 2*128*PADV + 32*PADV + 192) * 4)

__global__ __launch_bounds__(128)
void flash_kernel(const float* __restrict__ Q, const float* __restrict__ K,
                  const float* __restrict__ Vt, float* __restrict__ Oout)
{
    const int qt = 31 - (int)blockIdx.x;   // heavy blocks first
    const int bh = blockIdx.y;
    const int b = bh >> 1, h = bh & 1;
    const int q0 = qt * 32;
    const float scale = 0.08838834764831845f;  // 1/sqrt(128)

    extern __shared__ unsigned char smraw[];
    uint32_t* Qs  = (uint32_t*)smraw;           // [32][PADQ]  tf32
    uint32_t* Ks  = Qs + 32 * PADQ;             // [2][64][PADQ]  raw fp32
    uint32_t* Vs  = Ks + 2 * 64 * PADQ;         // [2][128][PADV] raw fp32
    uint32_t* Ps  = Vs + 2 * 128 * PADV;        // [32][PADV]  tf32
    float* m_s  = (float*)(Ps + 32 * PADV);     // [32]
    float* l_s  = m_s + 32;                     // [32]
    float* wmax = l_s + 32;                     // [2][32]
    float* wsum = wmax + 64;                    // [2][32]

    const int tid = threadIdx.x, lane = tid & 31, wid = tid >> 5;
    const int mh = wid >> 1;                    // m-half (16 rows)
    const int nh = wid & 1;                     // n-half
    const int grp = lane >> 3, lr = lane & 7;
    const int aRowOff = (grp & 1) * 8 + lr;
    const int aKoff   = (grp >> 1) * 4;
    const int bRowOff = (grp >> 1) * 8 + lr;
    const int bKoff   = (grp & 1) * 4;
    const int r0 = lane >> 2;
    const int cq = 2 * (lane & 3);

    const float* Qg = Q  + (size_t)bh * SEQ * DH;
    const float* Kg = K  + (size_t)bh * SEQ * DH;
    const float* Vg = Vt + (size_t)bh * DH * SEQ;

    const uint32_t ksAddr = (uint32_t)__cvta_generic_to_shared(Ks);
    const uint32_t vsAddr = (uint32_t)__cvta_generic_to_shared(Vs);

    // Q tile -> smem (tf32), 128 threads
    {
        const int r = tid >> 2, part = tid & 3;
        const float* src = Qg + (size_t)(q0 + r) * DH + part * 32;
        uint32_t* dst = Qs + r * PADQ + part * 32;
        #pragma unroll
        for (int j = 0; j < 8; j++) {
            float4 f = reinterpret_cast<const float4*>(src)[j];
            dst[j * 4 + 0] = f2tf32(f.x); dst[j * 4 + 1] = f2tf32(f.y);
            dst[j * 4 + 2] = f2tf32(f.z); dst[j * 4 + 3] = f2tf32(f.w);
        }
    }
    if (tid < 32) { m_s[tid] = -3.0e38f; l_s[tid] = 0.f; }

    const int nkt = (qt >> 1) + 1;

    // issue stage 0 K/V loads
    {
        #pragma unroll
        for (int i = 0; i < 16; i++) {       // K: 64x128 floats, 16B chunks
            const int c = tid + 128 * i;
            const int row = c >> 5, col = (c & 31) * 4;
            cp16(ksAddr + 4u * (row * PADQ + col), Kg + (size_t)row * DH + col);
        }
        #pragma unroll
        for (int i = 0; i < 16; i++) {       // V: 128x64 floats
            const int c = tid + 128 * i;
            const int row = c >> 4, col = (c & 15) * 4;
            cp16(vsAddr + 4u * (row * PADV + col), Vg + (size_t)row * SEQ + col);
        }
        CP_COMMIT();
    }

    float accO[8][4];
    #pragma unroll
    for (int i = 0; i < 8; i++)
        #pragma unroll
        for (int j = 0; j < 4; j++) accO[i][j] = 0.f;

    const int ridx0 = mh * 16 + r0, ridx1 = ridx0 + 8;

    for (int kt = 0; kt < nkt; kt++) {
        const int cur = kt & 1, nxt = cur ^ 1;
        const bool more = (kt + 1 < nkt);

        if (more) {   // issue next stage while current computes
            const uint32_t kd = ksAddr + 4u * (nxt * 64 * PADQ);
            const uint32_t vd = vsAddr + 4u * (nxt * 128 * PADV);
            #pragma unroll
            for (int i = 0; i < 16; i++) {
                const int c = tid + 128 * i;
                const int row = c >> 5, col = (c & 31) * 4;
                cp16(kd + 4u * (row * PADQ + col),
                     Kg + (size_t)((kt + 1) * 64 + row) * DH + col);
            }
            #pragma unroll
            for (int i = 0; i < 16; i++) {
                const int c = tid + 128 * i;
                const int row = c >> 4, col = (c & 15) * 4;
                cp16(vd + 4u * (row * PADV + col),
                     Vg + (size_t)row * SEQ + (kt + 1) * 64 + col);
            }
            CP_COMMIT();
            CP_WAIT1();
        } else {
            CP_WAIT0();
        }
        __syncthreads();

        // ---- S = Q K^T ----
        float accS[4][4];
        #pragma unroll
        for (int i = 0; i < 4; i++)
            #pragma unroll
            for (int j = 0; j < 4; j++) accS[i][j] = 0.f;

        const uint32_t qBase = (uint32_t)__cvta_generic_to_shared(Qs);
        const uint32_t kBase = ksAddr + 4u * (cur * 64 * PADQ);
        #pragma unroll
        for (int kc = 0; kc < 16; kc++) {
            uint32_t af[4], bf[4][2];
            {
                uint32_t addr = qBase + 4u * ((mh * 16 + aRowOff) * PADQ + kc * 8 + aKoff);
                ldm_x4(af[0], af[1], af[2], af[3], addr);
            }
            #pragma unroll
            for (int nt2 = 0; nt2 < 2; nt2++) {
                uint32_t t0, t1, t2, t3;
                uint32_t addr = kBase + 4u * ((nh * 32 + nt2 * 16 + bRowOff) * PADQ + kc * 8 + bKoff);
                ldm_x4(t0, t1, t2, t3, addr);
                bf[nt2 * 2 + 0][0] = u2tf32(t0); bf[nt2 * 2 + 0][1] = u2tf32(t1);
                bf[nt2 * 2 + 1][0] = u2tf32(t2); bf[nt2 * 2 + 1][1] = u2tf32(t3);
            }
            #pragma unroll
            for (int nt = 0; nt < 4; nt++)
                mma_tf32(accS[nt], af, bf[nt]);
        }

        // scale + causal mask + partial row max
        float pm0 = -3.0e38f, pm1 = -3.0e38f;
        #pragma unroll
        for (int nt = 0; nt < 4; nt++) {
            #pragma unroll
            for (int e = 0; e < 4; e++) {
                const int half = e >> 1, j = e & 1;
                const int col = kt * 64 + nh * 32 + nt * 8 + cq + j;
                const int qr = q0 + mh * 16 + r0 + half * 8;
                float v = accS[nt][e] * scale;
                if (col > qr) v = -1.0e30f;
                accS[nt][e] = v;
                if (half == 0) pm0 = fmaxf(pm0, v); else pm1 = fmaxf(pm1, v);
            }
        }
        pm0 = fmaxf(pm0, __shfl_xor_sync(0xffffffffu, pm0, 1));
        pm0 = fmaxf(pm0, __shfl_xor_sync(0xffffffffu, pm0, 2));
        pm1 = fmaxf(pm1, __shfl_xor_sync(0xffffffffu, pm1, 1));
        pm1 = fmaxf(pm1, __shfl_xor_sync(0xffffffffu, pm1, 2));
        if ((lane & 3) == 0) {
            wmax[nh * 32 + ridx0] = pm0;
            wmax[nh * 32 + ridx1] = pm1;
        }
        __syncthreads();

        const float mold0 = m_s[ridx0], mold1 = m_s[ridx1];
        const float nm0 = fmaxf(mold0, fmaxf(wmax[ridx0], wmax[32 + ridx0]));
        const float nm1 = fmaxf(mold1, fmaxf(wmax[ridx1], wmax[32 + ridx1]));
        const float fac0 = expf(mold0 - nm0);
        const float fac1 = expf(mold1 - nm1);

        float ps0 = 0.f, ps1 = 0.f;
        #pragma unroll
        for (int nt = 0; nt < 4; nt++) {
            #pragma unroll
            for (int e = 0; e < 4; e++) {
                const int half = e >> 1, j = e & 1;
                const float p = expf(accS[nt][e] - (half ? nm1 : nm0));
                if (half == 0) ps0 += p; else ps1 += p;
                const int col = nh * 32 + nt * 8 + cq + j;
                Ps[(mh * 16 + r0 + half * 8) * PADV + col] = f2tf32(p);
            }
        }
        ps0 += __shfl_xor_sync(0xffffffffu, ps0, 1);
        ps0 += __shfl_xor_sync(0xffffffffu, ps0, 2);
        ps1 += __shfl_xor_sync(0xffffffffu, ps1, 1);
        ps1 += __shfl_xor_sync(0xffffffffu, ps1, 2);
        if ((lane & 3) == 0) {
            wsum[nh * 32 + ridx0] = ps0;
            wsum[nh * 32 + ridx1] = ps1;
        }
        #pragma unroll
        for (int nt = 0; nt < 8; nt++) {
            accO[nt][0] *= fac0; accO[nt][1] *= fac0;
            accO[nt][2] *= fac1; accO[nt][3] *= fac1;
        }
        __syncthreads();

        if (nh == 0 && (lane & 3) == 0) {
            m_s[ridx0] = nm0;
            l_s[ridx0] = l_s[ridx0] * fac0 + wsum[ridx0] + wsum[32 + ridx0];
            m_s[ridx1] = nm1;
            l_s[ridx1] = l_s[ridx1] * fac1 + wsum[ridx1] + wsum[32 + ridx1];
        }

        // ---- O += P V ----
        const uint32_t pBase = (uint32_t)__cvta_generic_to_shared(Ps);
        const uint32_t vBase = vsAddr + 4u * (cur * 128 * PADV);
        #pragma unroll
        for (int kc = 0; kc < 8; kc++) {
            uint32_t af[4], bf[8][2];
            {
                uint32_t addr = pBase + 4u * ((mh * 16 + aRowOff) * PADV + kc * 8 + aKoff);
                ldm_x4(af[0], af[1], af[2], af[3], addr);
            }
            #pragma unroll
            for (int nt2 = 0; nt2 < 4; nt2++) {
                uint32_t t0, t1, t2, t3;
                uint32_t addr = vBase + 4u * ((nh * 64 + nt2 * 16 + bRowOff) * PADV + kc * 8 + bKoff);
                ldm_x4(t0, t1, t2, t3, addr);
                bf[nt2 * 2 + 0][0] = u2tf32(t0); bf[nt2 * 2 + 0][1] = u2tf32(t1);
                bf[nt2 * 2 + 1][0] = u2tf32(t2); bf[nt2 * 2 + 1][1] = u2tf32(t3);
            }
            #pragma unroll
            for (int nt = 0; nt < 8; nt++)
                mma_tf32(accO[nt], af, bf[nt]);
        }
        __syncthreads();
    }

    // normalize + write head-concat output
    const float inv0 = 1.f / l_s[ridx0];
    const float inv1 = 1.f / l_s[ridx1];
    #pragma unroll
    for (int nt = 0; nt < 8; nt++) {
        const int d = nh * 64 + nt * 8 + cq;
        const int s0 = q0 + ridx0;
        *reinterpret_cast<float2*>(&Oout[((size_t)(b * SEQ) + s0) * DIMS + h * DH + d]) =
            make_float2(accO[nt][0] * inv0, accO[nt][1] * inv0);
        *reinterpret_cast<float2*>(&Oout[((size_t)(b * SEQ) + s0 + 8) * DIMS + h * DH + d]) =
            make_float2(accO[nt][2] * inv1, accO[nt][3] * inv1);
    }
}

// ---------------- driver ----------------
extern "C" void kernel_launch(void* const* d_in, const int* in_sizes, int n_in,
                              void* d_out, int out_size)
{
    const int*   X     = (const int*)  d_in[0];
    const float* W_enc = (const float*)d_in[1];
    const float* b_enc = (const float*)d_in[2];
    const float* Wq    = (const float*)d_in[3];
    const float* Wk    = (const float*)d_in[4];
    const float* Wv    = (const float*)d_in[5];
    const float* Wo    = (const float*)d_in[6];
    const float* W1    = (const float*)d_in[7];
    const float* W2    = (const float*)d_in[8];
    const float* W_dec = (const float*)d_in[9];
    float* out = (float*)d_out;

    float *x, *q, *k, *vt, *attn, *a, *h;
    cudaGetSymbolAddress((void**)&x,    g_x);
    cudaGetSymbolAddress((void**)&q,    g_q);
    cudaGetSymbolAddress((void**)&k,    g_k);
    cudaGetSymbolAddress((void**)&vt,   g_vt);
    cudaGetSymbolAddress((void**)&attn, g_attn);
    cudaGetSymbolAddress((void**)&a,    g_a);
    cudaGetSymbolAddress((void**)&h,    g_h);

    cudaFuncSetAttribute(flash_kernel, cudaFuncAttributeMaxDynamicSharedMemorySize,
                         FLASH_SMEM);

    encode_kernel<<<TOKENS, 256>>>(X, W_enc, b_enc, x);

    const dim3 gQKV(DIMS / BN, TOKENS / BM, 3);      // 4 x 64 x 3 = 768
    const dim3 gSq (DIMS / BN, TOKENS / BM, 1);      // 256
    const dim3 gFl (32, NB * HEADS, 1);
    const dim3 gM1 (2 * DIMS / BN, TOKENS / BM, 1);  // 512
    const dim3 gDec(VOCAB / BN, TOKENS / BM, 1);     // 4096

    for (int l = 0; l < NLAYERS; l++) {
        const float* wq = Wq + (size_t)l * DIMS * DIMS;
        const float* wk = Wk + (size_t)l * DIMS * DIMS;
        const float* wv = Wv + (size_t)l * DIMS * DIMS;
        const float* wo = Wo + (size_t)l * DIMS * DIMS;
        const float* w1 = W1 + (size_t)l * DIMS * 2 * DIMS;
        const float* w2 = W2 + (size_t)l * 2 * DIMS * DIMS;

        gemm6<MODE_QKV><<<gQKV, 128>>>(x, wq, wk, wv, q, k, vt, nullptr,
                                       TOKENS, DIMS, DIMS);
        flash_kernel<<<gFl, 128, FLASH_SMEM>>>(q, k, vt, attn);
        gemm6<MODE_PLAIN><<<gSq, 128>>>(attn, wo, nullptr, nullptr, a, nullptr, nullptr, nullptr,
                                        TOKENS, DIMS, DIMS);
        gemm6<MODE_SILU><<<gM1, 128>>>(a, w1, nullptr, nullptr, h, nullptr, nullptr, nullptr,
                                       TOKENS, 2 * DIMS, DIMS);
        gemm6<MODE_RESADD><<<gSq, 128>>>(h, w2, nullptr, nullptr, x, nullptr, nullptr, x,
                                         TOKENS, DIMS, 2 * DIMS);
    }

    gemm6<MODE_PLAIN><<<gDec, 128>>>(x, W_dec, nullptr, nullptr, out, nullptr, nullptr, nullptr,
                                     TOKENS, VOCAB, DIMS);
}

// round 13
// speedup vs baseline: 2.2673x; 1.1164x over previous
#include <cuda_runtime.h>
#include <cuda_fp16.h>
#include <math.h>
#include <stdint.h>

#define DIMS    256
#define VOCAB   4096
#define HEADS   2
#define NB      2
#define SEQ     1024
#define DH      128
#define TOKENS  (NB * SEQ)
#define NLAYERS 6

// ---------------- scratch ----------------
__device__ float g_x[TOKENS * DIMS];
__device__ float g_q[NB * HEADS * SEQ * DH];     // [b,h,s,d]
__device__ float g_k[NB * HEADS * SEQ * DH];     // [b,h,s,d]
__device__ float g_vt[NB * HEADS * DH * SEQ];    // [b,h,d,s]
__device__ float g_attn[TOKENS * DIMS];
__device__ float g_a[TOKENS * DIMS];
__device__ float g_h[TOKENS * 2 * DIMS];

// ---------------- helpers ----------------
__device__ __forceinline__ uint32_t f2tf32(float f) {
    uint32_t r;
    asm("cvt.rna.tf32.f32 %0, %1;" : "=r"(r) : "f"(f));
    return r;
}
__device__ __forceinline__ uint32_t u2tf32(uint32_t u) {
    uint32_t r;
    asm("cvt.rna.tf32.f32 %0, %1;" : "=r"(r) : "f"(__uint_as_float(u)));
    return r;
}
__device__ __forceinline__ uint32_t pack_h2(float a, float b) {
    __half2 h = __floats2half2_rn(a, b);
    return *reinterpret_cast<uint32_t*>(&h);
}
__device__ __forceinline__ void ldm_x4(uint32_t& r0, uint32_t& r1, uint32_t& r2, uint32_t& r3,
                                       uint32_t addr) {
    asm volatile("ldmatrix.sync.aligned.m8n8.x4.shared.b16 {%0,%1,%2,%3}, [%4];"
                 : "=r"(r0), "=r"(r1), "=r"(r2), "=r"(r3) : "r"(addr));
}
__device__ __forceinline__ void mma_tf32(float* c, const uint32_t* a, const uint32_t* b) {
    asm volatile("mma.sync.aligned.m16n8k8.row.col.f32.tf32.tf32.f32 "
                 "{%0,%1,%2,%3}, {%4,%5,%6,%7}, {%8,%9}, {%0,%1,%2,%3};"
                 : "+f"(c[0]), "+f"(c[1]), "+f"(c[2]), "+f"(c[3])
                 : "r"(a[0]), "r"(a[1]), "r"(a[2]), "r"(a[3]), "r"(b[0]), "r"(b[1]));
}
__device__ __forceinline__ void mma_f16(float* c, const uint32_t* a, const uint32_t* b) {
    asm volatile("mma.sync.aligned.m16n8k16.row.col.f32.f16.f16.f32 "
                 "{%0,%1,%2,%3}, {%4,%5,%6,%7}, {%8,%9}, {%0,%1,%2,%3};"
                 : "+f"(c[0]), "+f"(c[1]), "+f"(c[2]), "+f"(c[3])
                 : "r"(a[0]), "r"(a[1]), "r"(a[2]), "r"(a[3]), "r"(b[0]), "r"(b[1]));
}
__device__ __forceinline__ void cp16(uint32_t dst, const void* src) {
    asm volatile("cp.async.cg.shared.global [%0], [%1], 16;" :: "r"(dst), "l"(src));
}
#define CP_COMMIT() asm volatile("cp.async.commit_group;" ::: "memory")
#define CP_WAIT1()  asm volatile("cp.async.wait_group 1;" ::: "memory")
#define CP_WAIT0()  asm volatile("cp.async.wait_group 0;" ::: "memory")

// ---------------- encoder ----------------
__global__ __launch_bounds__(256) void encode_kernel(
    const int* __restrict__ X, const float* __restrict__ W_enc,
    const float* __restrict__ b_enc, float* __restrict__ xout)
{
    const int t = blockIdx.x;
    const int s = t & (SEQ - 1);
    const int tid = threadIdx.x;

    __shared__ float pos[DIMS];
    {
        const int i = tid;
        const float p = (float)NB - (float)s;
        const int fi = (i < DH) ? i : i - DH;
        const float invf = 1.0f / powf(10000.0f, (float)fi * (1.0f / 128.0f));
        const float ang = p * invf;
        pos[i] = (i < DH) ? sinf(ang) : cosf(ang);
    }
    __syncthreads();

    const int tok = X[t];
    const int warp = tid >> 5, lane = tid & 31;

    #pragma unroll
    for (int o = warp; o < DIMS; o += 8) {
        const float* wrow = W_enc + ((size_t)o * VOCAB + tok) * DIMS;
        const float4* w4 = reinterpret_cast<const float4*>(wrow);
        const float4* p4 = reinterpret_cast<const float4*>(pos);
        float4 wa = w4[lane * 2 + 0], wb = w4[lane * 2 + 1];
        float4 pa = p4[lane * 2 + 0], pb = p4[lane * 2 + 1];
        float acc = wa.x * pa.x + wa.y * pa.y + wa.z * pa.z + wa.w * pa.w
                  + wb.x * pb.x + wb.y * pb.y + wb.z * pb.z + wb.w * pb.w;
        #pragma unroll
        for (int off = 16; off; off >>= 1)
            acc += __shfl_down_sync(0xffffffffu, acc, off);
        if (lane == 0)
            xout[t * DIMS + o] = acc + b_enc[o];
    }
}

// ---------------- fp16 tensor GEMM: BM=32, BN=64, BK=32, 128 thr / 4 warps ----
enum GemmMode {
    MODE_PLAIN = 0,
    MODE_QKV   = 1,   // z=0: Q [b,h,s,d]; z=1: K [b,h,s,d]; z=2: V^T [b,h,d,s]
    MODE_SILU  = 6,
    MODE_RESADD= 7
};

#define BM 32
#define BN 64
#define BK 32
#define PADH 40          // halves per smem row: 80B stride, 16B-aligned, conflict-free

template<int MODE>
__global__ __launch_bounds__(128)
void gemm7(const float* __restrict__ A,
           const float* __restrict__ B0, const float* __restrict__ B1, const float* __restrict__ B2,
           float* __restrict__ C0, float* __restrict__ C1, float* __restrict__ C2,
           const float* __restrict__ R,
           int M, int N, int K)
{
    const int z = blockIdx.z;
    const float* B = B0;
    float* C = C0;
    if (MODE == MODE_QKV) {
        B = (z == 0) ? B0 : (z == 1) ? B1 : B2;
        C = (z == 0) ? C0 : (z == 1) ? C1 : C2;
    }

    const int m0 = blockIdx.y * BM;
    const int n0 = blockIdx.x * BN;

    __shared__ __align__(16) uint16_t As[2][BM * PADH];
    __shared__ __align__(16) uint16_t Bs[2][BN * PADH];

    const int tid  = threadIdx.x;
    const int lane = tid & 31;
    const int wid  = tid >> 5;          // 4 warps
    const int wm   = wid >> 1;          // 0..1 -> m offset wm*16
    const int wn   = wid & 1;           // 0..1 -> n offset wn*32

    // A loader: 32 rows x 32 k; each thread 8 consecutive k
    const int aRow = tid >> 2;          // 0..31
    const int aCol = (tid & 3) * 8;     // 0,8,16,24 (halves = k elems)
    const float* gA = A + (size_t)(m0 + aRow) * K + aCol;

    // B loader: [n][k] store; each thread 16 k for one n
    const int bN = tid & 63;
    const int k0 = (tid >> 6) * 16;     // 0 or 16
    const float* gB = B + n0 + bN;

    // ldmatrix per-lane offsets (b16, 16-bit elements)
    const int grp = lane >> 3, lr = lane & 7;
    const int aRowOff = (grp & 1) * 8 + lr;
    const int aKoff   = (grp >> 1) * 8;      // halves
    const int bRowOff = (grp >> 1) * 8 + lr;
    const int bKoff   = (grp & 1) * 8;       // halves

    float acc[4][4];
    #pragma unroll
    for (int j = 0; j < 4; j++)
        #pragma unroll
        for (int r = 0; r < 4; r++) acc[j][r] = 0.f;

    const int nk = K / BK;

    // prologue: stage 0
    {
        float4 f0 = *reinterpret_cast<const float4*>(gA);
        float4 f1 = *reinterpret_cast<const float4*>(gA + 4);
        uint4 ua = make_uint4(pack_h2(f0.x, f0.y), pack_h2(f0.z, f0.w),
                              pack_h2(f1.x, f1.y), pack_h2(f1.z, f1.w));
        *reinterpret_cast<uint4*>(&As[0][aRow * PADH + aCol]) = ua;

        float rb[16];
        #pragma unroll
        for (int j = 0; j < 16; j++)
            rb[j] = gB[(size_t)(k0 + j) * N];
        uint4 ub0 = make_uint4(pack_h2(rb[0], rb[1]),  pack_h2(rb[2], rb[3]),
                               pack_h2(rb[4], rb[5]),  pack_h2(rb[6], rb[7]));
        uint4 ub1 = make_uint4(pack_h2(rb[8], rb[9]),  pack_h2(rb[10], rb[11]),
                               pack_h2(rb[12], rb[13]), pack_h2(rb[14], rb[15]));
        *reinterpret_cast<uint4*>(&Bs[0][bN * PADH + k0])     = ub0;
        *reinterpret_cast<uint4*>(&Bs[0][bN * PADH + k0 + 8]) = ub1;
    }
    __syncthreads();

    for (int kt = 0; kt < nk; kt++) {
        const int cur = kt & 1, nxt = cur ^ 1;
        float4 f0, f1;
        float rb[16];
        const bool more = (kt + 1 < nk);
        if (more) {
            const float* pA = gA + (kt + 1) * BK;
            f0 = *reinterpret_cast<const float4*>(pA);
            f1 = *reinterpret_cast<const float4*>(pA + 4);
            const float* pB = gB + (size_t)(kt + 1) * BK * N;
            #pragma unroll
            for (int j = 0; j < 16; j++)
                rb[j] = pB[(size_t)(k0 + j) * N];
        }

        const uint32_t aBase = (uint32_t)__cvta_generic_to_shared(&As[cur][0]);
        const uint32_t bBase = (uint32_t)__cvta_generic_to_shared(&Bs[cur][0]);

        #pragma unroll
        for (int kc = 0; kc < 2; kc++) {      // two k16 chunks
            uint32_t af[4], bf[4][2];
            {
                uint32_t addr = aBase + 2u * ((wm * 16 + aRowOff) * PADH + kc * 16 + aKoff);
                ldm_x4(af[0], af[1], af[2], af[3], addr);
            }
            #pragma unroll
            for (int nt2 = 0; nt2 < 2; nt2++) {
                uint32_t r0, r1, r2, r3;
                uint32_t addr = bBase + 2u * ((wn * 32 + nt2 * 16 + bRowOff) * PADH + kc * 16 + bKoff);
                ldm_x4(r0, r1, r2, r3, addr);
                bf[nt2 * 2 + 0][0] = r0; bf[nt2 * 2 + 0][1] = r1;
                bf[nt2 * 2 + 1][0] = r2; bf[nt2 * 2 + 1][1] = r3;
            }
            #pragma unroll
            for (int nt = 0; nt < 4; nt++)
                mma_f16(acc[nt], af, bf[nt]);
        }

        if (more) {
            uint4 ua = make_uint4(pack_h2(f0.x, f0.y), pack_h2(f0.z, f0.w),
                                  pack_h2(f1.x, f1.y), pack_h2(f1.z, f1.w));
            *reinterpret_cast<uint4*>(&As[nxt][aRow * PADH + aCol]) = ua;
            uint4 ub0 = make_uint4(pack_h2(rb[0], rb[1]),  pack_h2(rb[2], rb[3]),
                                   pack_h2(rb[4], rb[5]),  pack_h2(rb[6], rb[7]));
            uint4 ub1 = make_uint4(pack_h2(rb[8], rb[9]),  pack_h2(rb[10], rb[11]),
                                   pack_h2(rb[12], rb[13]), pack_h2(rb[14], rb[15]));
            *reinterpret_cast<uint4*>(&Bs[nxt][bN * PADH + k0])     = ub0;
            *reinterpret_cast<uint4*>(&Bs[nxt][bN * PADH + k0 + 8]) = ub1;
        }
        __syncthreads();
    }

    // epilogue (same accumulator layout as tf32 m16n8k8)
    #pragma unroll
    for (int nt = 0; nt < 4; nt++) {
        const int mrow = m0 + wm * 16 + (lane >> 2);
        const int ncol = n0 + wn * 32 + nt * 8 + 2 * (lane & 3);
        #pragma unroll
        for (int half = 0; half < 2; half++) {
            const int m = mrow + half * 8;
            float v0 = acc[nt][half * 2 + 0], v1 = acc[nt][half * 2 + 1];
            if (MODE == MODE_PLAIN) {
                *reinterpret_cast<float2*>(&C[(size_t)m * N + ncol]) = make_float2(v0, v1);
            } else if (MODE == MODE_SILU) {
                v0 = v0 / (1.f + expf(-v0));
                v1 = v1 / (1.f + expf(-v1));
                *reinterpret_cast<float2*>(&C[(size_t)m * N + ncol]) = make_float2(v0, v1);
            } else if (MODE == MODE_RESADD) {
                float2 r2 = *reinterpret_cast<const float2*>(&R[(size_t)m * N + ncol]);
                *reinterpret_cast<float2*>(&C[(size_t)m * N + ncol]) =
                    make_float2(v0 + r2.x, v1 + r2.y);
            } else if (MODE == MODE_QKV) {
                const int b = m / SEQ, srow = m & (SEQ - 1);
                const int h = ncol / DH, d = ncol & (DH - 1);
                if (z == 2) {  // V^T [b,h,d,s]
                    C[(((size_t)(b * HEADS + h) * DH) + d + 0) * SEQ + srow] = v0;
                    C[(((size_t)(b * HEADS + h) * DH) + d + 1) * SEQ + srow] = v1;
                } else {       // Q/K [b,h,s,d]
                    *reinterpret_cast<float2*>(
                        &C[(((size_t)(b * HEADS + h) * SEQ) + srow) * DH + d]) =
                        make_float2(v0, v1);
                }
            }
        }
    }
}

// ---------------- flash attention: 128 thr, cp.async double-buffered K/V ------
#define PADQ 132
#define PADV 68
#define FLASH_SMEM ((32*PADQ + 2*64*PADQ + 2*128*PADV + 32*PADV + 192) * 4)

__global__ __launch_bounds__(128)
void flash_kernel(const float* __restrict__ Q, const float* __restrict__ K,
                  const float* __restrict__ Vt, float* __restrict__ Oout)
{
    const int qt = 31 - (int)blockIdx.x;   // heavy blocks first
    const int bh = blockIdx.y;
    const int b = bh >> 1, h = bh & 1;
    const int q0 = qt * 32;
    const float scale = 0.08838834764831845f;  // 1/sqrt(128)

    extern __shared__ unsigned char smraw[];
    uint32_t* Qs  = (uint32_t*)smraw;           // [32][PADQ]  tf32
    uint32_t* Ks  = Qs + 32 * PADQ;             // [2][64][PADQ]  raw fp32
    uint32_t* Vs  = Ks + 2 * 64 * PADQ;         // [2][128][PADV] raw fp32
    uint32_t* Ps  = Vs + 2 * 128 * PADV;        // [32][PADV]  tf32
    float* m_s  = (float*)(Ps + 32 * PADV);     // [32]
    float* l_s  = m_s + 32;                     // [32]
    float* wmax = l_s + 32;                     // [2][32]
    float* wsum = wmax + 64;                    // [2][32]

    const int tid = threadIdx.x, lane = tid & 31, wid = tid >> 5;
    const int mh = wid >> 1;                    // m-half (16 rows)
    const int nh = wid & 1;                     // n-half
    const int grp = lane >> 3, lr = lane & 7;
    const int aRowOff = (grp & 1) * 8 + lr;
    const int aKoff   = (grp >> 1) * 4;
    const int bRowOff = (grp >> 1) * 8 + lr;
    const int bKoff   = (grp & 1) * 4;
    const int r0 = lane >> 2;
    const int cq = 2 * (lane & 3);

    const float* Qg = Q  + (size_t)bh * SEQ * DH;
    const float* Kg = K  + (size_t)bh * SEQ * DH;
    const float* Vg = Vt + (size_t)bh * DH * SEQ;

    const uint32_t ksAddr = (uint32_t)__cvta_generic_to_shared(Ks);
    const uint32_t vsAddr = (uint32_t)__cvta_generic_to_shared(Vs);

    // Q tile -> smem (tf32), 128 threads
    {
        const int r = tid >> 2, part = tid & 3;
        const float* src = Qg + (size_t)(q0 + r) * DH + part * 32;
        uint32_t* dst = Qs + r * PADQ + part * 32;
        #pragma unroll
        for (int j = 0; j < 8; j++) {
            float4 f = reinterpret_cast<const float4*>(src)[j];
            dst[j * 4 + 0] = f2tf32(f.x); dst[j * 4 + 1] = f2tf32(f.y);
            dst[j * 4 + 2] = f2tf32(f.z); dst[j * 4 + 3] = f2tf32(f.w);
        }
    }
    if (tid < 32) { m_s[tid] = -3.0e38f; l_s[tid] = 0.f; }

    const int nkt = (qt >> 1) + 1;

    // issue stage 0 K/V loads
    {
        #pragma unroll
        for (int i = 0; i < 16; i++) {       // K: 64x128 floats, 16B chunks
            const int c = tid + 128 * i;
            const int row = c >> 5, col = (c & 31) * 4;
            cp16(ksAddr + 4u * (row * PADQ + col), Kg + (size_t)row * DH + col);
        }
        #pragma unroll
        for (int i = 0; i < 16; i++) {       // V: 128x64 floats
            const int c = tid + 128 * i;
            const int row = c >> 4, col = (c & 15) * 4;
            cp16(vsAddr + 4u * (row * PADV + col), Vg + (size_t)row * SEQ + col);
        }
        CP_COMMIT();
    }

    float accO[8][4];
    #pragma unroll
    for (int i = 0; i < 8; i++)
        #pragma unroll
        for (int j = 0; j < 4; j++) accO[i][j] = 0.f;

    const int ridx0 = mh * 16 + r0, ridx1 = ridx0 + 8;

    for (int kt = 0; kt < nkt; kt++) {
        const int cur = kt & 1, nxt = cur ^ 1;
        const bool more = (kt + 1 < nkt);

        if (more) {   // issue next stage while current computes
            const uint32_t kd = ksAddr + 4u * (nxt * 64 * PADQ);
            const uint32_t vd = vsAddr + 4u * (nxt * 128 * PADV);
            #pragma unroll
            for (int i = 0; i < 16; i++) {
                const int c = tid + 128 * i;
                const int row = c >> 5, col = (c & 31) * 4;
                cp16(kd + 4u * (row * PADQ + col),
                     Kg + (size_t)((kt + 1) * 64 + row) * DH + col);
            }
            #pragma unroll
            for (int i = 0; i < 16; i++) {
                const int c = tid + 128 * i;
                const int row = c >> 4, col = (c & 15) * 4;
                cp16(vd + 4u * (row * PADV + col),
                     Vg + (size_t)row * SEQ + (kt + 1) * 64 + col);
            }
            CP_COMMIT();
            CP_WAIT1();
        } else {
            CP_WAIT0();
        }
        __syncthreads();

        // ---- S = Q K^T ----
        float accS[4][4];
        #pragma unroll
        for (int i = 0; i < 4; i++)
            #pragma unroll
            for (int j = 0; j < 4; j++) accS[i][j] = 0.f;

        const uint32_t qBase = (uint32_t)__cvta_generic_to_shared(Qs);
        const uint32_t kBase = ksAddr + 4u * (cur * 64 * PADQ);
        #pragma unroll
        for (int kc = 0; kc < 16; kc++) {
            uint32_t af[4], bf[4][2];
            {
                uint32_t addr = qBase + 4u * ((mh * 16 + aRowOff) * PADQ + kc * 8 + aKoff);
                ldm_x4(af[0], af[1], af[2], af[3], addr);
            }
            #pragma unroll
            for (int nt2 = 0; nt2 < 2; nt2++) {
                uint32_t t0, t1, t2, t3;
                uint32_t addr = kBase + 4u * ((nh * 32 + nt2 * 16 + bRowOff) * PADQ + kc * 8 + bKoff);
                ldm_x4(t0, t1, t2, t3, addr);
                bf[nt2 * 2 + 0][0] = u2tf32(t0); bf[nt2 * 2 + 0][1] = u2tf32(t1);
                bf[nt2 * 2 + 1][0] = u2tf32(t2); bf[nt2 * 2 + 1][1] = u2tf32(t3);
            }
            #pragma unroll
            for (int nt = 0; nt < 4; nt++)
                mma_tf32(accS[nt], af, bf[nt]);
        }

        // scale + causal mask + partial row max
        float pm0 = -3.0e38f, pm1 = -3.0e38f;
        #pragma unroll
        for (int nt = 0; nt < 4; nt++) {
            #pragma unroll
            for (int e = 0; e < 4; e++) {
                const int half = e >> 1, j = e & 1;
                const int col = kt * 64 + nh * 32 + nt * 8 + cq + j;
                const int qr = q0 + mh * 16 + r0 + half * 8;
                float v = accS[nt][e] * scale;
                if (col > qr) v = -1.0e30f;
                accS[nt][e] = v;
                if (half == 0) pm0 = fmaxf(pm0, v); else pm1 = fmaxf(pm1, v);
            }
        }
        pm0 = fmaxf(pm0, __shfl_xor_sync(0xffffffffu, pm0, 1));
        pm0 = fmaxf(pm0, __shfl_xor_sync(0xffffffffu, pm0, 2));
        pm1 = fmaxf(pm1, __shfl_xor_sync(0xffffffffu, pm1, 1));
        pm1 = fmaxf(pm1, __shfl_xor_sync(0xffffffffu, pm1, 2));
        if ((lane & 3) == 0) {
            wmax[nh * 32 + ridx0] = pm0;
            wmax[nh * 32 + ridx1] = pm1;
        }
        __syncthreads();

        const float mold0 = m_s[ridx0], mold1 = m_s[ridx1];
        const float nm0 = fmaxf(mold0, fmaxf(wmax[ridx0], wmax[32 + ridx0]));
        const float nm1 = fmaxf(mold1, fmaxf(wmax[ridx1], wmax[32 + ridx1]));
        const float fac0 = expf(mold0 - nm0);
        const float fac1 = expf(mold1 - nm1);

        float ps0 = 0.f, ps1 = 0.f;
        #pragma unroll
        for (int nt = 0; nt < 4; nt++) {
            #pragma unroll
            for (int e = 0; e < 4; e++) {
                const int half = e >> 1, j = e & 1;
                const float p = expf(accS[nt][e] - (half ? nm1 : nm0));
                if (half == 0) ps0 += p; else ps1 += p;
                const int col = nh * 32 + nt * 8 + cq + j;
                Ps[(mh * 16 + r0 + half * 8) * PADV + col] = f2tf32(p);
            }
        }
        ps0 += __shfl_xor_sync(0xffffffffu, ps0, 1);
        ps0 += __shfl_xor_sync(0xffffffffu, ps0, 2);
        ps1 += __shfl_xor_sync(0xffffffffu, ps1, 1);
        ps1 += __shfl_xor_sync(0xffffffffu, ps1, 2);
        if ((lane & 3) == 0) {
            wsum[nh * 32 + ridx0] = ps0;
            wsum[nh * 32 + ridx1] = ps1;
        }
        #pragma unroll
        for (int nt = 0; nt < 8; nt++) {
            accO[nt][0] *= fac0; accO[nt][1] *= fac0;
            accO[nt][2] *= fac1; accO[nt][3] *= fac1;
        }
        __syncthreads();

        if (nh == 0 && (lane & 3) == 0) {
            m_s[ridx0] = nm0;
            l_s[ridx0] = l_s[ridx0] * fac0 + wsum[ridx0] + wsum[32 + ridx0];
            m_s[ridx1] = nm1;
            l_s[ridx1] = l_s[ridx1] * fac1 + wsum[ridx1] + wsum[32 + ridx1];
        }

        // ---- O += P V ----
        const uint32_t pBase = (uint32_t)__cvta_generic_to_shared(Ps);
        const uint32_t vBase = vsAddr + 4u * (cur * 128 * PADV);
        #pragma unroll
        for (int kc = 0; kc < 8; kc++) {
            uint32_t af[4], bf[8][2];
            {
                uint32_t addr = pBase + 4u * ((mh * 16 + aRowOff) * PADV + kc * 8 + aKoff);
                ldm_x4(af[0], af[1], af[2], af[3], addr);
            }
            #pragma unroll
            for (int nt2 = 0; nt2 < 4; nt2++) {
                uint32_t t0, t1, t2, t3;
                uint32_t addr = vBase + 4u * ((nh * 64 + nt2 * 16 + bRowOff) * PADV + kc * 8 + bKoff);
                ldm_x4(t0, t1, t2, t3, addr);
                bf[nt2 * 2 + 0][0] = u2tf32(t0); bf[nt2 * 2 + 0][1] = u2tf32(t1);
                bf[nt2 * 2 + 1][0] = u2tf32(t2); bf[nt2 * 2 + 1][1] = u2tf32(t3);
            }
            #pragma unroll
            for (int nt = 0; nt < 8; nt++)
                mma_tf32(accO[nt], af, bf[nt]);
        }
        __syncthreads();
    }

    // normalize + write head-concat output
    const float inv0 = 1.f / l_s[ridx0];
    const float inv1 = 1.f / l_s[ridx1];
    #pragma unroll
    for (int nt = 0; nt < 8; nt++) {
        const int d = nh * 64 + nt * 8 + cq;
        const int s0 = q0 + ridx0;
        *reinterpret_cast<float2*>(&Oout[((size_t)(b * SEQ) + s0) * DIMS + h * DH + d]) =
            make_float2(accO[nt][0] * inv0, accO[nt][1] * inv0);
        *reinterpret_cast<float2*>(&Oout[((size_t)(b * SEQ) + s0 + 8) * DIMS + h * DH + d]) =
            make_float2(accO[nt][2] * inv1, accO[nt][3] * inv1);
    }
}

// ---------------- driver ----------------
extern "C" void kernel_launch(void* const* d_in, const int* in_sizes, int n_in,
                              void* d_out, int out_size)
{
    const int*   X     = (const int*)  d_in[0];
    const float* W_enc = (const float*)d_in[1];
    const float* b_enc = (const float*)d_in[2];
    const float* Wq    = (const float*)d_in[3];
    const float* Wk    = (const float*)d_in[4];
    const float* Wv    = (const float*)d_in[5];
    const float* Wo    = (const float*)d_in[6];
    const float* W1    = (const float*)d_in[7];
    const float* W2    = (const float*)d_in[8];
    const float* W_dec = (const float*)d_in[9];
    float* out = (float*)d_out;

    float *x, *q, *k, *vt, *attn, *a, *h;
    cudaGetSymbolAddress((void**)&x,    g_x);
    cudaGetSymbolAddress((void**)&q,    g_q);
    cudaGetSymbolAddress((void**)&k,    g_k);
    cudaGetSymbolAddress((void**)&vt,   g_vt);
    cudaGetSymbolAddress((void**)&attn, g_attn);
    cudaGetSymbolAddress((void**)&a,    g_a);
    cudaGetSymbolAddress((void**)&h,    g_h);

    cudaFuncSetAttribute(flash_kernel, cudaFuncAttributeMaxDynamicSharedMemorySize,
                         FLASH_SMEM);

    encode_kernel<<<TOKENS, 256>>>(X, W_enc, b_enc, x);

    const dim3 gQKV(DIMS / BN, TOKENS / BM, 3);      // 768
    const dim3 gSq (DIMS / BN, TOKENS / BM, 1);      // 256
    const dim3 gFl (32, NB * HEADS, 1);
    const dim3 gM1 (2 * DIMS / BN, TOKENS / BM, 1);  // 512
    const dim3 gDec(VOCAB / BN, TOKENS / BM, 1);     // 4096

    for (int l = 0; l < NLAYERS; l++) {
        const float* wq = Wq + (size_t)l * DIMS * DIMS;
        const float* wk = Wk + (size_t)l * DIMS * DIMS;
        const float* wv = Wv + (size_t)l * DIMS * DIMS;
        const float* wo = Wo + (size_t)l * DIMS * DIMS;
        const float* w1 = W1 + (size_t)l * DIMS * 2 * DIMS;
        const float* w2 = W2 + (size_t)l * 2 * DIMS * DIMS;

        gemm7<MODE_QKV><<<gQKV, 128>>>(x, wq, wk, wv, q, k, vt, nullptr,
                                       TOKENS, DIMS, DIMS);
        flash_kernel<<<gFl, 128, FLASH_SMEM>>>(q, k, vt, attn);
        gemm7<MODE_PLAIN><<<gSq, 128>>>(attn, wo, nullptr, nullptr, a, nullptr, nullptr, nullptr,
                                        TOKENS, DIMS, DIMS);
        gemm7<MODE_SILU><<<gM1, 128>>>(a, w1, nullptr, nullptr, h, nullptr, nullptr, nullptr,
                                       TOKENS, 2 * DIMS, DIMS);
        gemm7<MODE_RESADD><<<gSq, 128>>>(h, w2, nullptr, nullptr, x, nullptr, nullptr, x,
                                         TOKENS, DIMS, 2 * DIMS);
    }

    gemm7<MODE_PLAIN><<<gDec, 128>>>(x, W_dec, nullptr, nullptr, out, nullptr, nullptr, nullptr,
                                     TOKENS, VOCAB, DIMS);
}

// round 14
// speedup vs baseline: 2.6475x; 1.1677x over previous
#include <cuda_runtime.h>
#include <cuda_fp16.h>
#include <math.h>
#include <stdint.h>

#define DIMS    256
#define VOCAB   4096
#define HEADS   2
#define NB      2
#define SEQ     1024
#define DH      128
#define TOKENS  (NB * SEQ)
#define NLAYERS 6

// ---------------- scratch ----------------
__device__ float  g_x[TOKENS * DIMS];
__device__ __half g_qh[NB * HEADS * SEQ * DH];    // [b,h,s,d] fp16
__device__ __half g_kh[NB * HEADS * SEQ * DH];    // [b,h,s,d] fp16
__device__ __half g_vth[NB * HEADS * DH * SEQ];   // [b,h,d,s] fp16
__device__ float  g_attn[TOKENS * DIMS];
__device__ float  g_a[TOKENS * DIMS];
__device__ float  g_h[TOKENS * 2 * DIMS];

// ---------------- helpers ----------------
__device__ __forceinline__ uint32_t pack_h2(float a, float b) {
    __half2 h = __floats2half2_rn(a, b);
    return *reinterpret_cast<uint32_t*>(&h);
}
__device__ __forceinline__ void ldm_x4(uint32_t& r0, uint32_t& r1, uint32_t& r2, uint32_t& r3,
                                       uint32_t addr) {
    asm volatile("ldmatrix.sync.aligned.m8n8.x4.shared.b16 {%0,%1,%2,%3}, [%4];"
                 : "=r"(r0), "=r"(r1), "=r"(r2), "=r"(r3) : "r"(addr));
}
__device__ __forceinline__ void mma_f16(float* c, const uint32_t* a, const uint32_t* b) {
    asm volatile("mma.sync.aligned.m16n8k16.row.col.f32.f16.f16.f32 "
                 "{%0,%1,%2,%3}, {%4,%5,%6,%7}, {%8,%9}, {%0,%1,%2,%3};"
                 : "+f"(c[0]), "+f"(c[1]), "+f"(c[2]), "+f"(c[3])
                 : "r"(a[0]), "r"(a[1]), "r"(a[2]), "r"(a[3]), "r"(b[0]), "r"(b[1]));
}
__device__ __forceinline__ void cp16(uint32_t dst, const void* src) {
    asm volatile("cp.async.cg.shared.global [%0], [%1], 16;" :: "r"(dst), "l"(src));
}
#define CP_COMMIT() asm volatile("cp.async.commit_group;" ::: "memory")
#define CP_WAIT1()  asm volatile("cp.async.wait_group 1;" ::: "memory")
#define CP_WAIT0()  asm volatile("cp.async.wait_group 0;" ::: "memory")

// ---------------- encoder ----------------
__global__ __launch_bounds__(256) void encode_kernel(
    const int* __restrict__ X, const float* __restrict__ W_enc,
    const float* __restrict__ b_enc, float* __restrict__ xout)
{
    const int t = blockIdx.x;
    const int s = t & (SEQ - 1);
    const int tid = threadIdx.x;

    __shared__ float pos[DIMS];
    {
        const int i = tid;
        const float p = (float)NB - (float)s;
        const int fi = (i < DH) ? i : i - DH;
        const float invf = 1.0f / powf(10000.0f, (float)fi * (1.0f / 128.0f));
        const float ang = p * invf;
        pos[i] = (i < DH) ? sinf(ang) : cosf(ang);
    }
    __syncthreads();

    const int tok = X[t];
    const int warp = tid >> 5, lane = tid & 31;

    #pragma unroll
    for (int o = warp; o < DIMS; o += 8) {
        const float* wrow = W_enc + ((size_t)o * VOCAB + tok) * DIMS;
        const float4* w4 = reinterpret_cast<const float4*>(wrow);
        const float4* p4 = reinterpret_cast<const float4*>(pos);
        float4 wa = w4[lane * 2 + 0], wb = w4[lane * 2 + 1];
        float4 pa = p4[lane * 2 + 0], pb = p4[lane * 2 + 1];
        float acc = wa.x * pa.x + wa.y * pa.y + wa.z * pa.z + wa.w * pa.w
                  + wb.x * pb.x + wb.y * pb.y + wb.z * pb.z + wb.w * pb.w;
        #pragma unroll
        for (int off = 16; off; off >>= 1)
            acc += __shfl_down_sync(0xffffffffu, acc, off);
        if (lane == 0)
            xout[t * DIMS + o] = acc + b_enc[o];
    }
}

// ---------------- fp16 tensor GEMM: BM=32, BN=64, BK=32, 128 thr / 4 warps ----
enum GemmMode {
    MODE_PLAIN = 0,
    MODE_QKV   = 1,   // z=0: Q fp16 [b,h,s,d]; z=1: K fp16 [b,h,s,d]; z=2: V^T fp16 [b,h,d,s]
    MODE_SILU  = 6,
    MODE_RESADD= 7
};

#define BM 32
#define BN 64
#define BK 32
#define PADH 40          // halves per smem row: 80B stride, 16B-aligned, conflict-free

template<int MODE>
__global__ __launch_bounds__(128)
void gemm7(const float* __restrict__ A,
           const float* __restrict__ B0, const float* __restrict__ B1, const float* __restrict__ B2,
           void* __restrict__ C0v, void* __restrict__ C1v, void* __restrict__ C2v,
           const float* __restrict__ R,
           int M, int N, int K)
{
    const int z = blockIdx.z;
    const float* B = B0;
    void* Cv = C0v;
    if (MODE == MODE_QKV) {
        B = (z == 0) ? B0 : (z == 1) ? B1 : B2;
        Cv = (z == 0) ? C0v : (z == 1) ? C1v : C2v;
    }
    float* C = (float*)Cv;
    __half* Ch = (__half*)Cv;

    const int m0 = blockIdx.y * BM;
    const int n0 = blockIdx.x * BN;

    __shared__ __align__(16) uint16_t As[2][BM * PADH];
    __shared__ __align__(16) uint16_t Bs[2][BN * PADH];

    const int tid  = threadIdx.x;
    const int lane = tid & 31;
    const int wid  = tid >> 5;          // 4 warps
    const int wm   = wid >> 1;          // 0..1 -> m offset wm*16
    const int wn   = wid & 1;           // 0..1 -> n offset wn*32

    const int aRow = tid >> 2;          // 0..31
    const int aCol = (tid & 3) * 8;     // halves = k elems
    const float* gA = A + (size_t)(m0 + aRow) * K + aCol;

    const int bN = tid & 63;
    const int k0 = (tid >> 6) * 16;     // 0 or 16
    const float* gB = B + n0 + bN;

    const int grp = lane >> 3, lr = lane & 7;
    const int aRowOff = (grp & 1) * 8 + lr;
    const int aKoff   = (grp >> 1) * 8;
    const int bRowOff = (grp >> 1) * 8 + lr;
    const int bKoff   = (grp & 1) * 8;

    float acc[4][4];
    #pragma unroll
    for (int j = 0; j < 4; j++)
        #pragma unroll
        for (int r = 0; r < 4; r++) acc[j][r] = 0.f;

    const int nk = K / BK;

    // prologue: stage 0
    {
        float4 f0 = *reinterpret_cast<const float4*>(gA);
        float4 f1 = *reinterpret_cast<const float4*>(gA + 4);
        uint4 ua = make_uint4(pack_h2(f0.x, f0.y), pack_h2(f0.z, f0.w),
                              pack_h2(f1.x, f1.y), pack_h2(f1.z, f1.w));
        *reinterpret_cast<uint4*>(&As[0][aRow * PADH + aCol]) = ua;

        float rb[16];
        #pragma unroll
        for (int j = 0; j < 16; j++)
            rb[j] = gB[(size_t)(k0 + j) * N];
        uint4 ub0 = make_uint4(pack_h2(rb[0], rb[1]),  pack_h2(rb[2], rb[3]),
                               pack_h2(rb[4], rb[5]),  pack_h2(rb[6], rb[7]));
        uint4 ub1 = make_uint4(pack_h2(rb[8], rb[9]),  pack_h2(rb[10], rb[11]),
                               pack_h2(rb[12], rb[13]), pack_h2(rb[14], rb[15]));
        *reinterpret_cast<uint4*>(&Bs[0][bN * PADH + k0])     = ub0;
        *reinterpret_cast<uint4*>(&Bs[0][bN * PADH + k0 + 8]) = ub1;
    }
    __syncthreads();

    for (int kt = 0; kt < nk; kt++) {
        const int cur = kt & 1, nxt = cur ^ 1;
        float4 f0, f1;
        float rb[16];
        const bool more = (kt + 1 < nk);
        if (more) {
            const float* pA = gA + (kt + 1) * BK;
            f0 = *reinterpret_cast<const float4*>(pA);
            f1 = *reinterpret_cast<const float4*>(pA + 4);
            const float* pB = gB + (size_t)(kt + 1) * BK * N;
            #pragma unroll
            for (int j = 0; j < 16; j++)
                rb[j] = pB[(size_t)(k0 + j) * N];
        }

        const uint32_t aBase = (uint32_t)__cvta_generic_to_shared(&As[cur][0]);
        const uint32_t bBase = (uint32_t)__cvta_generic_to_shared(&Bs[cur][0]);

        #pragma unroll
        for (int kc = 0; kc < 2; kc++) {
            uint32_t af[4], bf[4][2];
            {
                uint32_t addr = aBase + 2u * ((wm * 16 + aRowOff) * PADH + kc * 16 + aKoff);
                ldm_x4(af[0], af[1], af[2], af[3], addr);
            }
            #pragma unroll
            for (int nt2 = 0; nt2 < 2; nt2++) {
                uint32_t r0, r1, r2, r3;
                uint32_t addr = bBase + 2u * ((wn * 32 + nt2 * 16 + bRowOff) * PADH + kc * 16 + bKoff);
                ldm_x4(r0, r1, r2, r3, addr);
                bf[nt2 * 2 + 0][0] = r0; bf[nt2 * 2 + 0][1] = r1;
                bf[nt2 * 2 + 1][0] = r2; bf[nt2 * 2 + 1][1] = r3;
            }
            #pragma unroll
            for (int nt = 0; nt < 4; nt++)
                mma_f16(acc[nt], af, bf[nt]);
        }

        if (more) {
            uint4 ua = make_uint4(pack_h2(f0.x, f0.y), pack_h2(f0.z, f0.w),
                                  pack_h2(f1.x, f1.y), pack_h2(f1.z, f1.w));
            *reinterpret_cast<uint4*>(&As[nxt][aRow * PADH + aCol]) = ua;
            uint4 ub0 = make_uint4(pack_h2(rb[0], rb[1]),  pack_h2(rb[2], rb[3]),
                                   pack_h2(rb[4], rb[5]),  pack_h2(rb[6], rb[7]));
            uint4 ub1 = make_uint4(pack_h2(rb[8], rb[9]),  pack_h2(rb[10], rb[11]),
                                   pack_h2(rb[12], rb[13]), pack_h2(rb[14], rb[15]));
            *reinterpret_cast<uint4*>(&Bs[nxt][bN * PADH + k0])     = ub0;
            *reinterpret_cast<uint4*>(&Bs[nxt][bN * PADH + k0 + 8]) = ub1;
        }
        __syncthreads();
    }

    // epilogue
    #pragma unroll
    for (int nt = 0; nt < 4; nt++) {
        const int mrow = m0 + wm * 16 + (lane >> 2);
        const int ncol = n0 + wn * 32 + nt * 8 + 2 * (lane & 3);
        #pragma unroll
        for (int half = 0; half < 2; half++) {
            const int m = mrow + half * 8;
            float v0 = acc[nt][half * 2 + 0], v1 = acc[nt][half * 2 + 1];
            if (MODE == MODE_PLAIN) {
                *reinterpret_cast<float2*>(&C[(size_t)m * N + ncol]) = make_float2(v0, v1);
            } else if (MODE == MODE_SILU) {
                v0 = v0 / (1.f + expf(-v0));
                v1 = v1 / (1.f + expf(-v1));
                *reinterpret_cast<float2*>(&C[(size_t)m * N + ncol]) = make_float2(v0, v1);
            } else if (MODE == MODE_RESADD) {
                float2 r2 = *reinterpret_cast<const float2*>(&R[(size_t)m * N + ncol]);
                *reinterpret_cast<float2*>(&C[(size_t)m * N + ncol]) =
                    make_float2(v0 + r2.x, v1 + r2.y);
            } else if (MODE == MODE_QKV) {
                const int b = m / SEQ, srow = m & (SEQ - 1);
                const int h = ncol / DH, d = ncol & (DH - 1);
                if (z == 2) {  // V^T fp16 [b,h,d,s]
                    Ch[(((size_t)(b * HEADS + h) * DH) + d + 0) * SEQ + srow] = __float2half(v0);
                    Ch[(((size_t)(b * HEADS + h) * DH) + d + 1) * SEQ + srow] = __float2half(v1);
                } else {       // Q/K fp16 [b,h,s,d]
                    __half2 hv = __floats2half2_rn(v0, v1);
                    *reinterpret_cast<__half2*>(
                        &Ch[(((size_t)(b * HEADS + h) * SEQ) + srow) * DH + d]) = hv;
                }
            }
        }
    }
}

// ---------------- flash attention: all-fp16 MMA, cp.async double-buffered ------
#define PADQH 136    // halves per 128-half row (272 B stride, conflict-free)
#define PADVH 72     // halves per 64-half row (144 B stride, conflict-free)
#define FLASH_SMEM ((32*PADQH + 2*64*PADQH + 2*128*PADVH + 32*PADVH) * 2 + 192 * 4)

__global__ __launch_bounds__(128)
void flash_kernel(const __half* __restrict__ Q, const __half* __restrict__ K,
                  const __half* __restrict__ Vt, float* __restrict__ Oout)
{
    const int qt = 31 - (int)blockIdx.x;   // heavy blocks first
    const int bh = blockIdx.y;
    const int b = bh >> 1, h = bh & 1;
    const int q0 = qt * 32;
    const float scale = 0.08838834764831845f;  // 1/sqrt(128)

    extern __shared__ unsigned char smraw[];
    uint16_t* Qs = (uint16_t*)smraw;            // [32][PADQH]
    uint16_t* Ks = Qs + 32 * PADQH;             // [2][64][PADQH]
    uint16_t* Vs = Ks + 2 * 64 * PADQH;         // [2][128][PADVH]
    uint16_t* Ps = Vs + 2 * 128 * PADVH;        // [32][PADVH]
    float* m_s  = (float*)(Ps + 32 * PADVH);    // [32]
    float* l_s  = m_s + 32;                     // [32]
    float* wmax = l_s + 32;                     // [2][32]
    float* wsum = wmax + 64;                    // [2][32]

    const int tid = threadIdx.x, lane = tid & 31, wid = tid >> 5;
    const int mh = wid >> 1;                    // m-half (16 rows)
    const int nh = wid & 1;                     // n-half
    const int grp = lane >> 3, lr = lane & 7;
    const int aRowOff = (grp & 1) * 8 + lr;
    const int aKoff   = (grp >> 1) * 8;         // halves
    const int bRowOff = (grp >> 1) * 8 + lr;
    const int bKoff   = (grp & 1) * 8;          // halves
    const int r0 = lane >> 2;
    const int cq = 2 * (lane & 3);

    const __half* Qg = Q  + (size_t)bh * SEQ * DH;
    const __half* Kg = K  + (size_t)bh * SEQ * DH;
    const __half* Vg = Vt + (size_t)bh * DH * SEQ;

    const uint32_t ksAddr = (uint32_t)__cvta_generic_to_shared(Ks);
    const uint32_t vsAddr = (uint32_t)__cvta_generic_to_shared(Vs);

    // Q tile -> smem (fp16 copy)
    {
        const int r = tid >> 2, part = tid & 3;   // 32 halves per (r,part)
        const uint4* src = reinterpret_cast<const uint4*>(Qg + (size_t)(q0 + r) * DH + part * 32);
        uint4* dst = reinterpret_cast<uint4*>(Qs + r * PADQH + part * 32);
        #pragma unroll
        for (int j = 0; j < 4; j++) dst[j] = src[j];
    }
    if (tid < 32) { m_s[tid] = -3.0e38f; l_s[tid] = 0.f; }

    const int nkt = (qt >> 1) + 1;

    // issue stage 0 K/V loads (16B = 8 halves per chunk)
    {
        #pragma unroll
        for (int i = 0; i < 8; i++) {        // K: 64x128 halves, 1024 chunks
            const int c = tid + 128 * i;
            const int row = c >> 4, ch = (c & 15) * 8;
            cp16(ksAddr + 2u * (row * PADQH + ch), Kg + (size_t)row * DH + ch);
        }
        #pragma unroll
        for (int i = 0; i < 8; i++) {        // V: 128x64 halves
            const int c = tid + 128 * i;
            const int row = c >> 3, ch = (c & 7) * 8;
            cp16(vsAddr + 2u * (row * PADVH + ch), Vg + (size_t)row * SEQ + ch);
        }
        CP_COMMIT();
    }

    float accO[8][4];
    #pragma unroll
    for (int i = 0; i < 8; i++)
        #pragma unroll
        for (int j = 0; j < 4; j++) accO[i][j] = 0.f;

    const int ridx0 = mh * 16 + r0, ridx1 = ridx0 + 8;

    for (int kt = 0; kt < nkt; kt++) {
        const int cur = kt & 1, nxt = cur ^ 1;
        const bool more = (kt + 1 < nkt);

        if (more) {
            const uint32_t kd = ksAddr + 2u * (nxt * 64 * PADQH);
            const uint32_t vd = vsAddr + 2u * (nxt * 128 * PADVH);
            #pragma unroll
            for (int i = 0; i < 8; i++) {
                const int c = tid + 128 * i;
                const int row = c >> 4, ch = (c & 15) * 8;
                cp16(kd + 2u * (row * PADQH + ch),
                     Kg + (size_t)((kt + 1) * 64 + row) * DH + ch);
            }
            #pragma unroll
            for (int i = 0; i < 8; i++) {
                const int c = tid + 128 * i;
                const int row = c >> 3, ch = (c & 7) * 8;
                cp16(vd + 2u * (row * PADVH + ch),
                     Vg + (size_t)row * SEQ + (kt + 1) * 64 + ch);
            }
            CP_COMMIT();
            CP_WAIT1();
        } else {
            CP_WAIT0();
        }
        __syncthreads();

        // ---- S = Q K^T (fp16, k16 steps) ----
        float accS[4][4];
        #pragma unroll
        for (int i = 0; i < 4; i++)
            #pragma unroll
            for (int j = 0; j < 4; j++) accS[i][j] = 0.f;

        const uint32_t qBase = (uint32_t)__cvta_generic_to_shared(Qs);
        const uint32_t kBase = ksAddr + 2u * (cur * 64 * PADQH);
        #pragma unroll
        for (int kc = 0; kc < 8; kc++) {
            uint32_t af[4], bf[4][2];
            {
                uint32_t addr = qBase + 2u * ((mh * 16 + aRowOff) * PADQH + kc * 16 + aKoff);
                ldm_x4(af[0], af[1], af[2], af[3], addr);
            }
            #pragma unroll
            for (int nt2 = 0; nt2 < 2; nt2++) {
                uint32_t t0, t1, t2, t3;
                uint32_t addr = kBase + 2u * ((nh * 32 + nt2 * 16 + bRowOff) * PADQH + kc * 16 + bKoff);
                ldm_x4(t0, t1, t2, t3, addr);
                bf[nt2 * 2 + 0][0] = t0; bf[nt2 * 2 + 0][1] = t1;
                bf[nt2 * 2 + 1][0] = t2; bf[nt2 * 2 + 1][1] = t3;
            }
            #pragma unroll
            for (int nt = 0; nt < 4; nt++)
                mma_f16(accS[nt], af, bf[nt]);
        }

        // scale + causal mask + partial row max
        float pm0 = -3.0e38f, pm1 = -3.0e38f;
        #pragma unroll
        for (int nt = 0; nt < 4; nt++) {
            #pragma unroll
            for (int e = 0; e < 4; e++) {
                const int half = e >> 1, j = e & 1;
                const int col = kt * 64 + nh * 32 + nt * 8 + cq + j;
                const int qr = q0 + mh * 16 + r0 + half * 8;
                float v = accS[nt][e] * scale;
                if (col > qr) v = -1.0e30f;
                accS[nt][e] = v;
                if (half == 0) pm0 = fmaxf(pm0, v); else pm1 = fmaxf(pm1, v);
            }
        }
        pm0 = fmaxf(pm0, __shfl_xor_sync(0xffffffffu, pm0, 1));
        pm0 = fmaxf(pm0, __shfl_xor_sync(0xffffffffu, pm0, 2));
        pm1 = fmaxf(pm1, __shfl_xor_sync(0xffffffffu, pm1, 1));
        pm1 = fmaxf(pm1, __shfl_xor_sync(0xffffffffu, pm1, 2));
        if ((lane & 3) == 0) {
            wmax[nh * 32 + ridx0] = pm0;
            wmax[nh * 32 + ridx1] = pm1;
        }
        __syncthreads();

        const float mold0 = m_s[ridx0], mold1 = m_s[ridx1];
        const float nm0 = fmaxf(mold0, fmaxf(wmax[ridx0], wmax[32 + ridx0]));
        const float nm1 = fmaxf(mold1, fmaxf(wmax[ridx1], wmax[32 + ridx1]));
        const float fac0 = expf(mold0 - nm0);
        const float fac1 = expf(mold1 - nm1);

        float ps0 = 0.f, ps1 = 0.f;
        #pragma unroll
        for (int nt = 0; nt < 4; nt++) {
            #pragma unroll
            for (int half = 0; half < 2; half++) {
                const float p0 = expf(accS[nt][half * 2 + 0] - (half ? nm1 : nm0));
                const float p1 = expf(accS[nt][half * 2 + 1] - (half ? nm1 : nm0));
                if (half == 0) ps0 += p0 + p1; else ps1 += p0 + p1;
                const int col = nh * 32 + nt * 8 + cq;
                *reinterpret_cast<__half2*>(
                    &Ps[(mh * 16 + r0 + half * 8) * PADVH + col]) = __floats2half2_rn(p0, p1);
            }
        }
        ps0 += __shfl_xor_sync(0xffffffffu, ps0, 1);
        ps0 += __shfl_xor_sync(0xffffffffu, ps0, 2);
        ps1 += __shfl_xor_sync(0xffffffffu, ps1, 1);
        ps1 += __shfl_xor_sync(0xffffffffu, ps1, 2);
        if ((lane & 3) == 0) {
            wsum[nh * 32 + ridx0] = ps0;
            wsum[nh * 32 + ridx1] = ps1;
        }
        #pragma unroll
        for (int nt = 0; nt < 8; nt++) {
            accO[nt][0] *= fac0; accO[nt][1] *= fac0;
            accO[nt][2] *= fac1; accO[nt][3] *= fac1;
        }
        __syncthreads();

        if (nh == 0 && (lane & 3) == 0) {
            m_s[ridx0] = nm0;
            l_s[ridx0] = l_s[ridx0] * fac0 + wsum[ridx0] + wsum[32 + ridx0];
            m_s[ridx1] = nm1;
            l_s[ridx1] = l_s[ridx1] * fac1 + wsum[ridx1] + wsum[32 + ridx1];
        }

        // ---- O += P V (fp16, k16 steps over 64 keys) ----
        const uint32_t pBase = (uint32_t)__cvta_generic_to_shared(Ps);
        const uint32_t vBase = vsAddr + 2u * (cur * 128 * PADVH);
        #pragma unroll
        for (int kc = 0; kc < 4; kc++) {
            uint32_t af[4], bf[8][2];
            {
                uint32_t addr = pBase + 2u * ((mh * 16 + aRowOff) * PADVH + kc * 16 + aKoff);
                ldm_x4(af[0], af[1], af[2], af[3], addr);
            }
            #pragma unroll
            for (int nt2 = 0; nt2 < 4; nt2++) {
                uint32_t t0, t1, t2, t3;
                uint32_t addr = vBase + 2u * ((nh * 64 + nt2 * 16 + bRowOff) * PADVH + kc * 16 + bKoff);
                ldm_x4(t0, t1, t2, t3, addr);
                bf[nt2 * 2 + 0][0] = t0; bf[nt2 * 2 + 0][1] = t1;
                bf[nt2 * 2 + 1][0] = t2; bf[nt2 * 2 + 1][1] = t3;
            }
            #pragma unroll
            for (int nt = 0; nt < 8; nt++)
                mma_f16(accO[nt], af, bf[nt]);
        }
        __syncthreads();
    }

    // normalize + write head-concat output
    const float inv0 = 1.f / l_s[ridx0];
    const float inv1 = 1.f / l_s[ridx1];
    #pragma unroll
    for (int nt = 0; nt < 8; nt++) {
        const int d = nh * 64 + nt * 8 + cq;
        const int s0 = q0 + ridx0;
        *reinterpret_cast<float2*>(&Oout[((size_t)(b * SEQ) + s0) * DIMS + h * DH + d]) =
            make_float2(accO[nt][0] * inv0, accO[nt][1] * inv0);
        *reinterpret_cast<float2*>(&Oout[((size_t)(b * SEQ) + s0 + 8) * DIMS + h * DH + d]) =
            make_float2(accO[nt][2] * inv1, accO[nt][3] * inv1);
    }
}

// ---------------- driver ----------------
extern "C" void kernel_launch(void* const* d_in, const int* in_sizes, int n_in,
                              void* d_out, int out_size)
{
    const int*   X     = (const int*)  d_in[0];
    const float* W_enc = (const float*)d_in[1];
    const float* b_enc = (const float*)d_in[2];
    const float* Wq    = (const float*)d_in[3];
    const float* Wk    = (const float*)d_in[4];
    const float* Wv    = (const float*)d_in[5];
    const float* Wo    = (const float*)d_in[6];
    const float* W1    = (const float*)d_in[7];
    const float* W2    = (const float*)d_in[8];
    const float* W_dec = (const float*)d_in[9];
    float* out = (float*)d_out;

    float *x, *attn, *a, *h;
    __half *qh, *kh, *vth;
    cudaGetSymbolAddress((void**)&x,    g_x);
    cudaGetSymbolAddress((void**)&qh,   g_qh);
    cudaGetSymbolAddress((void**)&kh,   g_kh);
    cudaGetSymbolAddress((void**)&vth,  g_vth);
    cudaGetSymbolAddress((void**)&attn, g_attn);
    cudaGetSymbolAddress((void**)&a,    g_a);
    cudaGetSymbolAddress((void**)&h,    g_h);

    cudaFuncSetAttribute(flash_kernel, cudaFuncAttributeMaxDynamicSharedMemorySize,
                         FLASH_SMEM);

    encode_kernel<<<TOKENS, 256>>>(X, W_enc, b_enc, x);

    const dim3 gQKV(DIMS / BN, TOKENS / BM, 3);      // 768
    const dim3 gSq (DIMS / BN, TOKENS / BM, 1);      // 256
    const dim3 gFl (32, NB * HEADS, 1);
    const dim3 gM1 (2 * DIMS / BN, TOKENS / BM, 1);  // 512
    const dim3 gDec(VOCAB / BN, TOKENS / BM, 1);     // 4096

    for (int l = 0; l < NLAYERS; l++) {
        const float* wq = Wq + (size_t)l * DIMS * DIMS;
        const float* wk = Wk + (size_t)l * DIMS * DIMS;
        const float* wv = Wv + (size_t)l * DIMS * DIMS;
        const float* wo = Wo + (size_t)l * DIMS * DIMS;
        const float* w1 = W1 + (size_t)l * DIMS * 2 * DIMS;
        const float* w2 = W2 + (size_t)l * 2 * DIMS * DIMS;

        gemm7<MODE_QKV><<<gQKV, 128>>>(x, wq, wk, wv, qh, kh, vth, nullptr,
                                       TOKENS, DIMS, DIMS);
        flash_kernel<<<gFl, 128, FLASH_SMEM>>>(qh, kh, vth, attn);
        gemm7<MODE_PLAIN><<<gSq, 128>>>(attn, wo, nullptr, nullptr, a, nullptr, nullptr, nullptr,
                                        TOKENS, DIMS, DIMS);
        gemm7<MODE_SILU><<<gM1, 128>>>(a, w1, nullptr, nullptr, h, nullptr, nullptr, nullptr,
                                       TOKENS, 2 * DIMS, DIMS);
        gemm7<MODE_RESADD><<<gSq, 128>>>(h, w2, nullptr, nullptr, x, nullptr, nullptr, x,
                                         TOKENS, DIMS, 2 * DIMS);
    }

    gemm7<MODE_PLAIN><<<gDec, 128>>>(x, W_dec, nullptr, nullptr, out, nullptr, nullptr, nullptr,
                                     TOKENS, VOCAB, DIMS);
}

// round 17
// speedup vs baseline: 3.0980x; 1.1702x over previous
#include <cuda_runtime.h>
#include <cuda_fp16.h>
#include <math.h>
#include <stdint.h>

#define DIMS    256
#define VOCAB   4096
#define HEADS   2
#define NB      2
#define SEQ     1024
#define DH      128
#define TOKENS  (NB * SEQ)
#define NLAYERS 6

// ---------------- scratch ----------------
__device__ float  g_x[TOKENS * DIMS];             // residual (fp32)
__device__ __half g_xh[TOKENS * DIMS];            // fp16 mirror of x
__device__ __half g_qh[NB * HEADS * SEQ * DH];    // [b,h,s,d]
__device__ __half g_kh[NB * HEADS * SEQ * DH];    // [b,h,s,d]
__device__ __half g_vth[NB * HEADS * DH * SEQ];   // [b,h,d,s]
__device__ __half g_attnh[TOKENS * DIMS];
__device__ __half g_ah[TOKENS * DIMS];
__device__ __half g_hh[TOKENS * 2 * DIMS];
// pre-transposed fp16 weights  [n][k]
__device__ __half g_wqT[NLAYERS * DIMS * DIMS];
__device__ __half g_wkT[NLAYERS * DIMS * DIMS];
__device__ __half g_wvT[NLAYERS * DIMS * DIMS];
__device__ __half g_woT[NLAYERS * DIMS * DIMS];
__device__ __half g_w1T[NLAYERS * 2 * DIMS * DIMS];   // [512][256] per layer
__device__ __half g_w2T[NLAYERS * DIMS * 2 * DIMS];   // [256][512] per layer
__device__ __half g_wdT[VOCAB * DIMS];                // [4096][256]

// ---------------- helpers ----------------
__device__ __forceinline__ void ldm_x4(uint32_t& r0, uint32_t& r1, uint32_t& r2, uint32_t& r3,
                                       uint32_t addr) {
    asm volatile("ldmatrix.sync.aligned.m8n8.x4.shared.b16 {%0,%1,%2,%3}, [%4];"
                 : "=r"(r0), "=r"(r1), "=r"(r2), "=r"(r3) : "r"(addr));
}
__device__ __forceinline__ void mma_f16(float* c, const uint32_t* a, const uint32_t* b) {
    asm volatile("mma.sync.aligned.m16n8k16.row.col.f32.f16.f16.f32 "
                 "{%0,%1,%2,%3}, {%4,%5,%6,%7}, {%8,%9}, {%0,%1,%2,%3};"
                 : "+f"(c[0]), "+f"(c[1]), "+f"(c[2]), "+f"(c[3])
                 : "r"(a[0]), "r"(a[1]), "r"(a[2]), "r"(a[3]), "r"(b[0]), "r"(b[1]));
}
__device__ __forceinline__ void cp16(uint32_t dst, const void* src) {
    asm volatile("cp.async.cg.shared.global [%0], [%1], 16;" :: "r"(dst), "l"(src));
}
#define CP_COMMIT() asm volatile("cp.async.commit_group;" ::: "memory")
#define CP_WAIT2()  asm volatile("cp.async.wait_group 2;" ::: "memory")
#define CP_WAIT1()  asm volatile("cp.async.wait_group 1;" ::: "memory")
#define CP_WAIT0()  asm volatile("cp.async.wait_group 0;" ::: "memory")

// ---------------- weight prep: fp32 [k][n] -> fp16 [n][k] ----------------
// 4096 tiles of 32x32. id map: [0,1536) qkvo; [1536,2304) W1; [2304,3072) W2; [3072,4096) Wdec
__global__ __launch_bounds__(256) void prep_weights(
    const float* __restrict__ Wq, const float* __restrict__ Wk,
    const float* __restrict__ Wv, const float* __restrict__ Wo,
    const float* __restrict__ W1, const float* __restrict__ W2,
    const float* __restrict__ Wd)
{
    const int id = blockIdx.x;
    const float* src; __half* dst;
    int K, N, tx, ty;
    if (id < 1536) {
        const int mat = id >> 6, t = id & 63;
        const int l = mat >> 2, w = mat & 3;
        src = (w == 0 ? Wq : w == 1 ? Wk : w == 2 ? Wv : Wo) + (size_t)l * DIMS * DIMS;
        dst = (w == 0 ? g_wqT : w == 1 ? g_wkT : w == 2 ? g_wvT : g_woT) + (size_t)l * DIMS * DIMS;
        K = 256; N = 256; ty = t >> 3; tx = t & 7;
    } else if (id < 2304) {
        const int r = id - 1536, l = r >> 7, t = r & 127;
        src = W1 + (size_t)l * DIMS * 2 * DIMS;
        dst = g_w1T + (size_t)l * 2 * DIMS * DIMS;
        K = 256; N = 512; ty = t >> 4; tx = t & 15;
    } else if (id < 3072) {
        const int r = id - 2304, l = r >> 7, t = r & 127;
        src = W2 + (size_t)l * DIMS * 2 * DIMS;
        dst = g_w2T + (size_t)l * DIMS * 2 * DIMS;
        K = 512; N = 256; ty = t >> 3; tx = t & 7;
    } else {
        const int t = id - 3072;
        src = Wd; dst = g_wdT;
        K = 256; N = 4096; ty = t >> 7; tx = t & 127;
    }

    __shared__ __half tile[32][40];
    const int c = threadIdx.x & 31, r0 = threadIdx.x >> 5;
    #pragma unroll
    for (int r = r0; r < 32; r += 8)
        tile[r][c] = __float2half(src[(size_t)(ty * 32 + r) * N + tx * 32 + c]);
    __syncthreads();
    #pragma unroll
    for (int r = r0; r < 32; r += 8)
        dst[(size_t)(tx * 32 + r) * K + ty * 32 + c] = tile[c][r];
}

// ---------------- encoder (writes fp32 x + fp16 mirror) ----------------
__global__ __launch_bounds__(256) void encode_kernel(
    const int* __restrict__ X, const float* __restrict__ W_enc,
    const float* __restrict__ b_enc, float* __restrict__ xout, __half* __restrict__ xh)
{
    const int t = blockIdx.x;
    const int s = t & (SEQ - 1);
    const int tid = threadIdx.x;

    __shared__ float pos[DIMS];
    {
        const int i = tid;
        const float p = (float)NB - (float)s;
        const int fi = (i < DH) ? i : i - DH;
        const float invf = 1.0f / powf(10000.0f, (float)fi * (1.0f / 128.0f));
        const float ang = p * invf;
        pos[i] = (i < DH) ? sinf(ang) : cosf(ang);
    }
    __syncthreads();

    const int tok = X[t];
    const int warp = tid >> 5, lane = tid & 31;

    #pragma unroll
    for (int o = warp; o < DIMS; o += 8) {
        const float* wrow = W_enc + ((size_t)o * VOCAB + tok) * DIMS;
        const float4* w4 = reinterpret_cast<const float4*>(wrow);
        const float4* p4 = reinterpret_cast<const float4*>(pos);
        float4 wa = w4[lane * 2 + 0], wb = w4[lane * 2 + 1];
        float4 pa = p4[lane * 2 + 0], pb = p4[lane * 2 + 1];
        float acc = wa.x * pa.x + wa.y * pa.y + wa.z * pa.z + wa.w * pa.w
                  + wb.x * pb.x + wb.y * pb.y + wb.z * pb.z + wb.w * pb.w;
        #pragma unroll
        for (int off = 16; off; off >>= 1)
            acc += __shfl_down_sync(0xffffffffu, acc, off);
        if (lane == 0) {
            acc += b_enc[o];
            xout[t * DIMS + o] = acc;
            xh[t * DIMS + o] = __float2half(acc);
        }
    }
}

// ---------------- gemm8: all-fp16, cp.async 4-stage pipeline ----------------
enum GemmMode {
    M_PLAIN = 0,   // fp32 out
    M_QKV   = 1,   // z=0 Q, z=1 K (fp16 [b,h,s,d]), z=2 V^T (fp16 [b,h,d,s])
    M_H     = 2,   // fp16 out
    M_SILUH = 3,   // silu, fp16 out
    M_RES   = 4    // R + v -> fp32 C + fp16 mirror Mh
};

#define BM 32
#define BN 64
#define BK 32
#define PADH 40
#define A_STAGE (BM * PADH)     // halves
#define B_STAGE (BN * PADH)
#define STAGES 4

template<int MODE>
__global__ __launch_bounds__(128)
void gemm8(const __half* __restrict__ A,
           const __half* __restrict__ B0, const __half* __restrict__ B1, const __half* __restrict__ B2,
           void* __restrict__ C0v, void* __restrict__ C1v, void* __restrict__ C2v,
           const float* __restrict__ R, __half* __restrict__ Mh,
           int M, int N, int K)
{
    const int z = blockIdx.z;
    const __half* B = B0;
    void* Cv = C0v;
    if (MODE == M_QKV) {
        B = (z == 0) ? B0 : (z == 1) ? B1 : B2;
        Cv = (z == 0) ? C0v : (z == 1) ? C1v : C2v;
    }
    float* C = (float*)Cv;
    __half* Ch = (__half*)Cv;

    const int m0 = blockIdx.y * BM;
    const int n0 = blockIdx.x * BN;

    __shared__ __align__(16) uint16_t As[STAGES * A_STAGE];
    __shared__ __align__(16) uint16_t Bs[STAGES * B_STAGE];

    const int tid  = threadIdx.x;
    const int lane = tid & 31;
    const int wid  = tid >> 5;
    const int wm   = wid >> 1;
    const int wn   = wid & 1;

    const uint32_t aSm = (uint32_t)__cvta_generic_to_shared(As);
    const uint32_t bSm = (uint32_t)__cvta_generic_to_shared(Bs);

    // loader mappings
    const int aRow = tid >> 2, aCh = (tid & 3) * 8;            // A: 128 chunks
    const int bRow0 = tid >> 2, bCh0 = (tid & 3) * 8;          // B chunk i=0
    const int bRow1 = (tid + 128) >> 2, bCh1 = ((tid + 128) & 3) * 8;

    const __half* gA = A + (size_t)(m0 + aRow) * K + aCh;
    const __half* gB0 = B + (size_t)(n0 + bRow0) * K + bCh0;
    const __half* gB1 = B + (size_t)(n0 + bRow1) * K + bCh1;

    const int grp = lane >> 3, lr = lane & 7;
    const int aRowOff = (grp & 1) * 8 + lr;
    const int aKoff   = (grp >> 1) * 8;
    const int bRowOff = (grp >> 1) * 8 + lr;
    const int bKoff   = (grp & 1) * 8;

    float acc[4][4];
    #pragma unroll
    for (int j = 0; j < 4; j++)
        #pragma unroll
        for (int r = 0; r < 4; r++) acc[j][r] = 0.f;

    const int nk = K / BK;

    // prologue: issue stages 0..2
    #pragma unroll
    for (int p = 0; p < 3; p++) {
        cp16(aSm + 2u * (p * A_STAGE + aRow * PADH + aCh), gA + p * BK);
        cp16(bSm + 2u * (p * B_STAGE + bRow0 * PADH + bCh0), gB0 + p * BK);
        cp16(bSm + 2u * (p * B_STAGE + bRow1 * PADH + bCh1), gB1 + p * BK);
        CP_COMMIT();
    }

    for (int kt = 0; kt < nk; kt++) {
        CP_WAIT2();
        __syncthreads();
        const int st = kt & (STAGES - 1);

        #pragma unroll
        for (int kc = 0; kc < 2; kc++) {
            uint32_t af[4], bf[4][2];
            {
                uint32_t addr = aSm + 2u * (st * A_STAGE + (wm * 16 + aRowOff) * PADH + kc * 16 + aKoff);
                ldm_x4(af[0], af[1], af[2], af[3], addr);
            }
            #pragma unroll
            for (int nt2 = 0; nt2 < 2; nt2++) {
                uint32_t r0, r1, r2, r3;
                uint32_t addr = bSm + 2u * (st * B_STAGE + (wn * 32 + nt2 * 16 + bRowOff) * PADH + kc * 16 + bKoff);
                ldm_x4(r0, r1, r2, r3, addr);
                bf[nt2 * 2 + 0][0] = r0; bf[nt2 * 2 + 0][1] = r1;
                bf[nt2 * 2 + 1][0] = r2; bf[nt2 * 2 + 1][1] = r3;
            }
            #pragma unroll
            for (int nt = 0; nt < 4; nt++)
                mma_f16(acc[nt], af, bf[nt]);
        }

        if (kt + 3 < nk) {
            const int ns = (kt + 3) & (STAGES - 1);
            cp16(aSm + 2u * (ns * A_STAGE + aRow * PADH + aCh), gA + (kt + 3) * BK);
            cp16(bSm + 2u * (ns * B_STAGE + bRow0 * PADH + bCh0), gB0 + (kt + 3) * BK);
            cp16(bSm + 2u * (ns * B_STAGE + bRow1 * PADH + bCh1), gB1 + (kt + 3) * BK);
        }
        CP_COMMIT();
    }

    // epilogue
    #pragma unroll
    for (int nt = 0; nt < 4; nt++) {
        const int mrow = m0 + wm * 16 + (lane >> 2);
        const int ncol = n0 + wn * 32 + nt * 8 + 2 * (lane & 3);
        #pragma unroll
        for (int half = 0; half < 2; half++) {
            const int m = mrow + half * 8;
            float v0 = acc[nt][half * 2 + 0], v1 = acc[nt][half * 2 + 1];
            if (MODE == M_PLAIN) {
                *reinterpret_cast<float2*>(&C[(size_t)m * N + ncol]) = make_float2(v0, v1);
            } else if (MODE == M_H) {
                *reinterpret_cast<__half2*>(&Ch[(size_t)m * N + ncol]) = __floats2half2_rn(v0, v1);
            } else if (MODE == M_SILUH) {
                v0 = v0 / (1.f + expf(-v0));
                v1 = v1 / (1.f + expf(-v1));
                *reinterpret_cast<__half2*>(&Ch[(size_t)m * N + ncol]) = __floats2half2_rn(v0, v1);
            } else if (MODE == M_RES) {
                float2 r2 = *reinterpret_cast<const float2*>(&R[(size_t)m * N + ncol]);
                v0 += r2.x; v1 += r2.y;
                *reinterpret_cast<float2*>(&C[(size_t)m * N + ncol]) = make_float2(v0, v1);
                *reinterpret_cast<__half2*>(&Mh[(size_t)m * N + ncol]) = __floats2half2_rn(v0, v1);
            } else if (MODE == M_QKV) {
                const int b = m / SEQ, srow = m & (SEQ - 1);
                const int h = ncol / DH, d = ncol & (DH - 1);
                if (z == 2) {
                    Ch[(((size_t)(b * HEADS + h) * DH) + d + 0) * SEQ + srow] = __float2half(v0);
                    Ch[(((size_t)(b * HEADS + h) * DH) + d + 1) * SEQ + srow] = __float2half(v1);
                } else {
                    *reinterpret_cast<__half2*>(
                        &Ch[(((size_t)(b * HEADS + h) * SEQ) + srow) * DH + d]) =
                        __floats2half2_rn(v0, v1);
                }
            }
        }
    }
}

// ---------------- flash attention: all-fp16 MMA, cp.async double-buffered ------
#define PADQH 136
#define PADVH 72
#define FLASH_SMEM ((32*PADQH + 2*64*PADQH + 2*128*PADVH + 32*PADVH) * 2 + 192 * 4)

__global__ __launch_bounds__(128)
void flash_kernel(const __half* __restrict__ Q, const __half* __restrict__ K,
                  const __half* __restrict__ Vt, __half* __restrict__ Oout)
{
    const int qt = 31 - (int)blockIdx.x;
    const int bh = blockIdx.y;
    const int b = bh >> 1, h = bh & 1;
    const int q0 = qt * 32;
    const float scale = 0.08838834764831845f;

    extern __shared__ unsigned char smraw[];
    uint16_t* Qs = (uint16_t*)smraw;
    uint16_t* Ks = Qs + 32 * PADQH;
    uint16_t* Vs = Ks + 2 * 64 * PADQH;
    uint16_t* Ps = Vs + 2 * 128 * PADVH;
    float* m_s  = (float*)(Ps + 32 * PADVH);
    float* l_s  = m_s + 32;
    float* wmax = l_s + 32;
    float* wsum = wmax + 64;

    const int tid = threadIdx.x, lane = tid & 31, wid = tid >> 5;
    const int mh = wid >> 1;
    const int nh = wid & 1;
    const int grp = lane >> 3, lr = lane & 7;
    const int aRowOff = (grp & 1) * 8 + lr;
    const int aKoff   = (grp >> 1) * 8;
    const int bRowOff = (grp >> 1) * 8 + lr;
    const int bKoff   = (grp & 1) * 8;
    const int r0 = lane >> 2;
    const int cq = 2 * (lane & 3);

    const __half* Qg = Q  + (size_t)bh * SEQ * DH;
    const __half* Kg = K  + (size_t)bh * SEQ * DH;
    const __half* Vg = Vt + (size_t)bh * DH * SEQ;

    const uint32_t ksAddr = (uint32_t)__cvta_generic_to_shared(Ks);
    const uint32_t vsAddr = (uint32_t)__cvta_generic_to_shared(Vs);

    {
        const int r = tid >> 2, part = tid & 3;
        const uint4* src = reinterpret_cast<const uint4*>(Qg + (size_t)(q0 + r) * DH + part * 32);
        uint4* dst = reinterpret_cast<uint4*>(Qs + r * PADQH + part * 32);
        #pragma unroll
        for (int j = 0; j < 4; j++) dst[j] = src[j];
    }
    if (tid < 32) { m_s[tid] = -3.0e38f; l_s[tid] = 0.f; }

    const int nkt = (qt >> 1) + 1;

    {
        #pragma unroll
        for (int i = 0; i < 8; i++) {
            const int c = tid + 128 * i;
            const int row = c >> 4, ch = (c & 15) * 8;
            cp16(ksAddr + 2u * (row * PADQH + ch), Kg + (size_t)row * DH + ch);
        }
        #pragma unroll
        for (int i = 0; i < 8; i++) {
            const int c = tid + 128 * i;
            const int row = c >> 3, ch = (c & 7) * 8;
            cp16(vsAddr + 2u * (row * PADVH + ch), Vg + (size_t)row * SEQ + ch);
        }
        CP_COMMIT();
    }

    float accO[8][4];
    #pragma unroll
    for (int i = 0; i < 8; i++)
        #pragma unroll
        for (int j = 0; j < 4; j++) accO[i][j] = 0.f;

    const int ridx0 = mh * 16 + r0, ridx1 = ridx0 + 8;

    for (int kt = 0; kt < nkt; kt++) {
        const int cur = kt & 1, nxt = cur ^ 1;
        const bool more = (kt + 1 < nkt);

        if (more) {
            const uint32_t kd = ksAddr + 2u * (nxt * 64 * PADQH);
            const uint32_t vd = vsAddr + 2u * (nxt * 128 * PADVH);
            #pragma unroll
            for (int i = 0; i < 8; i++) {
                const int c = tid + 128 * i;
                const int row = c >> 4, ch = (c & 15) * 8;
                cp16(kd + 2u * (row * PADQH + ch),
                     Kg + (size_t)((kt + 1) * 64 + row) * DH + ch);
            }
            #pragma unroll
            for (int i = 0; i < 8; i++) {
                const int c = tid + 128 * i;
                const int row = c >> 3, ch = (c & 7) * 8;
                cp16(vd + 2u * (row * PADVH + ch),
                     Vg + (size_t)row * SEQ + (kt + 1) * 64 + ch);
            }
            CP_COMMIT();
            CP_WAIT1();
        } else {
            CP_WAIT0();
        }
        __syncthreads();

        float accS[4][4];
        #pragma unroll
        for (int i = 0; i < 4; i++)
            #pragma unroll
            for (int j = 0; j < 4; j++) accS[i][j] = 0.f;

        const uint32_t qBase = (uint32_t)__cvta_generic_to_shared(Qs);
        const uint32_t kBase = ksAddr + 2u * (cur * 64 * PADQH);
        #pragma unroll
        for (int kc = 0; kc < 8; kc++) {
            uint32_t af[4], bf[4][2];
            {
                uint32_t addr = qBase + 2u * ((mh * 16 + aRowOff) * PADQH + kc * 16 + aKoff);
                ldm_x4(af[0], af[1], af[2], af[3], addr);
            }
            #pragma unroll
            for (int nt2 = 0; nt2 < 2; nt2++) {
                uint32_t t0, t1, t2, t3;
                uint32_t addr = kBase + 2u * ((nh * 32 + nt2 * 16 + bRowOff) * PADQH + kc * 16 + bKoff);
                ldm_x4(t0, t1, t2, t3, addr);
                bf[nt2 * 2 + 0][0] = t0; bf[nt2 * 2 + 0][1] = t1;
                bf[nt2 * 2 + 1][0] = t2; bf[nt2 * 2 + 1][1] = t3;
            }
            #pragma unroll
            for (int nt = 0; nt < 4; nt++)
                mma_f16(accS[nt], af, bf[nt]);
        }

        float pm0 = -3.0e38f, pm1 = -3.0e38f;
        #pragma unroll
        for (int nt = 0; nt < 4; nt++) {
            #pragma unroll
            for (int e = 0; e < 4; e++) {
                const int half = e >> 1, j = e & 1;
                const int col = kt * 64 + nh * 32 + nt * 8 + cq + j;
                const int qr = q0 + mh * 16 + r0 + half * 8;
                float v = accS[nt][e] * scale;
                if (col > qr) v = -1.0e30f;
                accS[nt][e] = v;
                if (half == 0) pm0 = fmaxf(pm0, v); else pm1 = fmaxf(pm1, v);
            }
        }
        pm0 = fmaxf(pm0, __shfl_xor_sync(0xffffffffu, pm0, 1));
        pm0 = fmaxf(pm0, __shfl_xor_sync(0xffffffffu, pm0, 2));
        pm1 = fmaxf(pm1, __shfl_xor_sync(0xffffffffu, pm1, 1));
        pm1 = fmaxf(pm1, __shfl_xor_sync(0xffffffffu, pm1, 2));
        if ((lane & 3) == 0) {
            wmax[nh * 32 + ridx0] = pm0;
            wmax[nh * 32 + ridx1] = pm1;
        }
        __syncthreads();

        const float mold0 = m_s[ridx0], mold1 = m_s[ridx1];
        const float nm0 = fmaxf(mold0, fmaxf(wmax[ridx0], wmax[32 + ridx0]));
        const float nm1 = fmaxf(mold1, fmaxf(wmax[ridx1], wmax[32 + ridx1]));
        const float fac0 = expf(mold0 - nm0);
        const float fac1 = expf(mold1 - nm1);

        float ps0 = 0.f, ps1 = 0.f;
        #pragma unroll
        for (int nt = 0; nt < 4; nt++) {
            #pragma unroll
            for (int half = 0; half < 2; half++) {
                const float p0 = expf(accS[nt][half * 2 + 0] - (half ? nm1 : nm0));
                const float p1 = expf(accS[nt][half * 2 + 1] - (half ? nm1 : nm0));
                if (half == 0) ps0 += p0 + p1; else ps1 += p0 + p1;
                const int col = nh * 32 + nt * 8 + cq;
                *reinterpret_cast<__half2*>(
                    &Ps[(mh * 16 + r0 + half * 8) * PADVH + col]) = __floats2half2_rn(p0, p1);
            }
        }
        ps0 += __shfl_xor_sync(0xffffffffu, ps0, 1);
        ps0 += __shfl_xor_sync(0xffffffffu, ps0, 2);
        ps1 += __shfl_xor_sync(0xffffffffu, ps1, 1);
        ps1 += __shfl_xor_sync(0xffffffffu, ps1, 2);
        if ((lane & 3) == 0) {
            wsum[nh * 32 + ridx0] = ps0;
            wsum[nh * 32 + ridx1] = ps1;
        }
        #pragma unroll
        for (int nt = 0; nt < 8; nt++) {
            accO[nt][0] *= fac0; accO[nt][1] *= fac0;
            accO[nt][2] *= fac1; accO[nt][3] *= fac1;
        }
        __syncthreads();

        if (nh == 0 && (lane & 3) == 0) {
            m_s[ridx0] = nm0;
            l_s[ridx0] = l_s[ridx0] * fac0 + wsum[ridx0] + wsum[32 + ridx0];
            m_s[ridx1] = nm1;
            l_s[ridx1] = l_s[ridx1] * fac1 + wsum[ridx1] + wsum[32 + ridx1];
        }

        const uint32_t pBase = (uint32_t)__cvta_generic_to_shared(Ps);
        const uint32_t vBase = vsAddr + 2u * (cur * 128 * PADVH);
        #pragma unroll
        for (int kc = 0; kc < 4; kc++) {
            uint32_t af[4], bf[8][2];
            {
                uint32_t addr = pBase + 2u * ((mh * 16 + aRowOff) * PADVH + kc * 16 + aKoff);
                ldm_x4(af[0], af[1], af[2], af[3], addr);
            }
            #pragma unroll
            for (int nt2 = 0; nt2 < 4; nt2++) {
                uint32_t t0, t1, t2, t3;
                uint32_t addr = vBase + 2u * ((nh * 64 + nt2 * 16 + bRowOff) * PADVH + kc * 16 + bKoff);
                ldm_x4(t0, t1, t2, t3, addr);
                bf[nt2 * 2 + 0][0] = t0; bf[nt2 * 2 + 0][1] = t1;
                bf[nt2 * 2 + 1][0] = t2; bf[nt2 * 2 + 1][1] = t3;
            }
            #pragma unroll
            for (int nt = 0; nt < 8; nt++)
                mma_f16(accO[nt], af, bf[nt]);
        }
        __syncthreads();
    }

    const float inv0 = 1.f / l_s[ridx0];
    const float inv1 = 1.f / l_s[ridx1];
    #pragma unroll
    for (int nt = 0; nt < 8; nt++) {
        const int d = nh * 64 + nt * 8 + cq;
        const int s0 = q0 + ridx0;
        *reinterpret_cast<__half2*>(&Oout[((size_t)(b * SEQ) + s0) * DIMS + h * DH + d]) =
            __floats2half2_rn(accO[nt][0] * inv0, accO[nt][1] * inv0);
        *reinterpret_cast<__half2*>(&Oout[((size_t)(b * SEQ) + s0 + 8) * DIMS + h * DH + d]) =
            __floats2half2_rn(accO[nt][2] * inv1, accO[nt][3] * inv1);
    }
}

// ---------------- driver ----------------
extern "C" void kernel_launch(void* const* d_in, const int* in_sizes, int n_in,
                              void* d_out, int out_size)
{
    const int*   X     = (const int*)  d_in[0];
    const float* W_enc = (const float*)d_in[1];
    const float* b_enc = (const float*)d_in[2];
    const float* Wq    = (const float*)d_in[3];
    const float* Wk    = (const float*)d_in[4];
    const float* Wv    = (const float*)d_in[5];
    const float* Wo    = (const float*)d_in[6];
    const float* W1    = (const float*)d_in[7];
    const float* W2    = (const float*)d_in[8];
    const float* W_dec = (const float*)d_in[9];
    float* out = (float*)d_out;

    float *x;
    __half *xh, *qh, *kh, *vth, *attnh, *ah, *hh;
    __half *wqT, *wkT, *wvT, *woT, *w1T, *w2T, *wdT;
    cudaGetSymbolAddress((void**)&x,     g_x);
    cudaGetSymbolAddress((void**)&xh,    g_xh);
    cudaGetSymbolAddress((void**)&qh,    g_qh);
    cudaGetSymbolAddress((void**)&kh,    g_kh);
    cudaGetSymbolAddress((void**)&vth,   g_vth);
    cudaGetSymbolAddress((void**)&attnh, g_attnh);
    cudaGetSymbolAddress((void**)&ah,    g_ah);
    cudaGetSymbolAddress((void**)&hh,    g_hh);
    cudaGetSymbolAddress((void**)&wqT,   g_wqT);
    cudaGetSymbolAddress((void**)&wkT,   g_wkT);
    cudaGetSymbolAddress((void**)&wvT,   g_wvT);
    cudaGetSymbolAddress((void**)&woT,   g_woT);
    cudaGetSymbolAddress((void**)&w1T,   g_w1T);
    cudaGetSymbolAddress((void**)&w2T,   g_w2T);
    cudaGetSymbolAddress((void**)&wdT,   g_wdT);

    cudaFuncSetAttribute(flash_kernel, cudaFuncAttributeMaxDynamicSharedMemorySize,
                         FLASH_SMEM);

    prep_weights<<<4096, 256>>>(Wq, Wk, Wv, Wo, W1, W2, W_dec);
    encode_kernel<<<TOKENS, 256>>>(X, W_enc, b_enc, x, xh);

    const dim3 gQKV(DIMS / BN, TOKENS / BM, 3);
    const dim3 gSq (DIMS / BN, TOKENS / BM, 1);
    const dim3 gFl (32, NB * HEADS, 1);
    const dim3 gM1 (2 * DIMS / BN, TOKENS / BM, 1);
    const dim3 gDec(VOCAB / BN, TOKENS / BM, 1);

    for (int l = 0; l < NLAYERS; l++) {
        __half* wqTl = wqT + (size_t)l * DIMS * DIMS;
        __half* wkTl = wkT + (size_t)l * DIMS * DIMS;
        __half* wvTl = wvT + (size_t)l * DIMS * DIMS;
        __half* woTl = woT + (size_t)l * DIMS * DIMS;
        __half* w1Tl = w1T + (size_t)l * 2 * DIMS * DIMS;
        __half* w2Tl = w2T + (size_t)l * DIMS * 2 * DIMS;

        gemm8<M_QKV><<<gQKV, 128>>>(xh, wqTl, wkTl, wvTl, qh, kh, vth,
                                    nullptr, nullptr, TOKENS, DIMS, DIMS);
        flash_kernel<<<gFl, 128, FLASH_SMEM>>>(qh, kh, vth, attnh);
        gemm8<M_H><<<gSq, 128>>>(attnh, woTl, nullptr, nullptr, ah, nullptr, nullptr,
                                 nullptr, nullptr, TOKENS, DIMS, DIMS);
        gemm8<M_SILUH><<<gM1, 128>>>(ah, w1Tl, nullptr, nullptr, hh, nullptr, nullptr,
                                     nullptr, nullptr, TOKENS, 2 * DIMS, DIMS);
        gemm8<M_RES><<<gSq, 128>>>(hh, w2Tl, nullptr, nullptr, x, nullptr, nullptr,
                                   x, xh, TOKENS, DIMS, 2 * DIMS);
    }

    gemm8<M_PLAIN><<<gDec, 128>>>(xh, wdT, nullptr, nullptr, out, nullptr, nullptr,
                                  nullptr, nullptr, TOKENS, VOCAB, DIMS);
}